// round 1
// baseline (speedup 1.0000x reference)
#include <cuda_runtime.h>
#include <cuda_bf16.h>

// ---------------- scratch (no allocation allowed) ----------------
#define BS 8
#define SEQ 512
#define DM 512
#define NROW (BS*SEQ)          // 4096
__device__ float g_qkv[NROW * 1024];   // [Q(256) | K(256) | V(512)] for self
__device__ float g_kvenc[NROW * 768];  // [K(256) | V(512)] for encoder
__device__ float g_q2[NROW * 256];     // Q of cross attention
__device__ float g_fx[NROW * 512];     // self-attn output
__device__ float g_fx2[NROW * 512];    // cross-attn output

// ---------------- SGEMM: C[M,N] = A[M,K] @ B[K,N], all row-major ----------------
// grid = (N/128, M/128), 256 threads. K % 8 == 0, M % 128 == 0, N % 128 == 0.
#define BM 128
#define BN 128
#define BKC 8
#define TM 8
#define TN 8

__global__ __launch_bounds__(256) void sgemm_k(
    const float* __restrict__ A, int lda,
    const float* __restrict__ B, int ldb,
    float* __restrict__ C, int ldc, int K)
{
    __shared__ __align__(16) float As[BKC][BM];
    __shared__ __align__(16) float Bs[BKC][BN];

    const int tid  = threadIdx.x;
    const int crow = blockIdx.y * BM;
    const int ccol = blockIdx.x * BN;

    A += crow * lda;
    B += ccol;
    C += crow * ldc + ccol;

    const int aRow = tid >> 1;          // 0..127
    const int aCol = (tid & 1) << 2;    // 0 or 4
    const int bRow = tid >> 5;          // 0..7
    const int bCol = (tid & 31) << 2;   // 0..124

    const int tr = (tid >> 4) * TM;     // 0..120
    const int tc = (tid & 15) * TN;     // 0..120

    float acc[TM][TN];
#pragma unroll
    for (int i = 0; i < TM; i++)
#pragma unroll
        for (int j = 0; j < TN; j++) acc[i][j] = 0.f;

    for (int k0 = 0; k0 < K; k0 += BKC) {
        float4 a = *(const float4*)(A + aRow * lda + k0 + aCol);
        As[aCol + 0][aRow] = a.x;
        As[aCol + 1][aRow] = a.y;
        As[aCol + 2][aRow] = a.z;
        As[aCol + 3][aRow] = a.w;
        *(float4*)(&Bs[bRow][bCol]) = *(const float4*)(B + (k0 + bRow) * ldb + bCol);
        __syncthreads();

#pragma unroll
        for (int k = 0; k < BKC; k++) {
            float4 m0 = *(const float4*)(&As[k][tr]);
            float4 m1 = *(const float4*)(&As[k][tr + 4]);
            float4 n0 = *(const float4*)(&Bs[k][tc]);
            float4 n1 = *(const float4*)(&Bs[k][tc + 4]);
            float rm[TM] = {m0.x, m0.y, m0.z, m0.w, m1.x, m1.y, m1.z, m1.w};
            float rn[TN] = {n0.x, n0.y, n0.z, n0.w, n1.x, n1.y, n1.z, n1.w};
#pragma unroll
            for (int i = 0; i < TM; i++)
#pragma unroll
                for (int j = 0; j < TN; j++)
                    acc[i][j] = fmaf(rm[i], rn[j], acc[i][j]);
        }
        __syncthreads();
    }

#pragma unroll
    for (int i = 0; i < TM; i++) {
#pragma unroll
        for (int j = 0; j < TN; j += 4) {
            float4 v = make_float4(acc[i][j], acc[i][j+1], acc[i][j+2], acc[i][j+3]);
            *(float4*)(C + (tr + i) * ldc + tc + j) = v;
        }
    }
}

// ---------------- Attention ----------------
// grid = B*HEAD (512) blocks, 512 threads (one query per thread).
// K rows (512 x 4) and V rows (512 x 8) in shared; broadcast LDS reads.
// Faithful quirk: with CAUSAL, masked scores are 0 (not -inf) and participate
// in the softmax (weights exp(0-m)/denom multiply masked V rows too).
template <int CAUSAL>
__global__ __launch_bounds__(512) void attn_k(
    const float* __restrict__ Qbuf, int ldq, int qoff,
    const float* __restrict__ KVbuf, int ldkv, int koff, int voff,
    float* __restrict__ Out)
{
    __shared__ float4 sK[SEQ];
    __shared__ float4 sV[SEQ * 2];

    const int bh = blockIdx.x;
    const int h  = bh & 63;
    const int b  = bh >> 6;
    const int t  = threadIdx.x;
    const int rowbase = b * SEQ + t;

    const float* kv = KVbuf + rowbase * ldkv;
    sK[t]         = *(const float4*)(kv + koff + h * 4);
    sV[2 * t]     = *(const float4*)(kv + voff + h * 8);
    sV[2 * t + 1] = *(const float4*)(kv + voff + h * 8 + 4);
    __syncthreads();

    const int q = t;
    const float4 qv = *(const float4*)(Qbuf + rowbase * ldq + qoff + h * 4);
    const float q0 = qv.x * 0.5f, q1 = qv.y * 0.5f, q2 = qv.z * 0.5f, q3 = qv.w * 0.5f;

    // pass 1: max (masked entries contribute score 0)
    float m = -1e30f;
#pragma unroll 4
    for (int k = 0; k < SEQ; k++) {
        float4 kk = sK[k];
        float s = fmaf(q0, kk.x, fmaf(q1, kk.y, fmaf(q2, kk.z, q3 * kk.w)));
        if (CAUSAL && k > q) s = 0.f;
        m = fmaxf(m, s);
    }

    // pass 2: denom + weighted V
    float denom = 0.f;
    float a0 = 0, a1 = 0, a2 = 0, a3 = 0, a4 = 0, a5 = 0, a6 = 0, a7 = 0;
#pragma unroll 4
    for (int k = 0; k < SEQ; k++) {
        float4 kk = sK[k];
        float s = fmaf(q0, kk.x, fmaf(q1, kk.y, fmaf(q2, kk.z, q3 * kk.w)));
        if (CAUSAL && k > q) s = 0.f;
        float p = __expf(s - m);
        denom += p;
        float4 v0 = sV[2 * k];
        float4 v1 = sV[2 * k + 1];
        a0 = fmaf(p, v0.x, a0); a1 = fmaf(p, v0.y, a1);
        a2 = fmaf(p, v0.z, a2); a3 = fmaf(p, v0.w, a3);
        a4 = fmaf(p, v1.x, a4); a5 = fmaf(p, v1.y, a5);
        a6 = fmaf(p, v1.z, a6); a7 = fmaf(p, v1.w, a7);
    }
    const float inv = 1.0f / denom;
    float* o = Out + rowbase * DM + h * 8;
    *(float4*)(o)     = make_float4(a0 * inv, a1 * inv, a2 * inv, a3 * inv);
    *(float4*)(o + 4) = make_float4(a4 * inv, a5 * inv, a6 * inv, a7 * inv);
}

// ---------------- Residual + LayerNorm + FFN (hidden=10) fused ----------------
// grid = 4096 rows, 256 threads (2 cols per thread).
#define HIDD 10
__global__ __launch_bounds__(256) void lnffn_k(
    const float* __restrict__ x, const float* __restrict__ fx,
    const float* __restrict__ lg, const float* __restrict__ lb,
    const float* __restrict__ w1, const float* __restrict__ b1,
    const float* __restrict__ w2, const float* __restrict__ b2,
    float* __restrict__ out)
{
    const int row = blockIdx.x;
    const int t = threadIdx.x;
    const int warp = t >> 5, lane = t & 31;

    const float* xr = x + row * DM;
    const float* fr = fx + row * DM;
    float v0 = xr[t] + fr[t];
    float v1 = xr[t + 256] + fr[t + 256];

    float s = v0 + v1;
    float ss = v0 * v0 + v1 * v1;
#pragma unroll
    for (int o = 16; o > 0; o >>= 1) {
        s  += __shfl_down_sync(0xffffffffu, s,  o);
        ss += __shfl_down_sync(0xffffffffu, ss, o);
    }
    __shared__ float rs[8], rss[8];
    if (lane == 0) { rs[warp] = s; rss[warp] = ss; }
    __syncthreads();
    float S = 0.f, SS = 0.f;
#pragma unroll
    for (int w = 0; w < 8; w++) { S += rs[w]; SS += rss[w]; }
    const float mu = S * (1.0f / DM);
    const float var = SS * (1.0f / DM) - mu * mu;
    const float rstd = rsqrtf(var + 1e-5f);

    const float y0 = (v0 - mu) * rstd * lg[t] + lb[t];
    const float y1 = (v1 - mu) * rstd * lg[t + 256] + lb[t + 256];

    // h[j] = relu(sum_c y_c * w1[j,c] + b1[j])
    float pj[HIDD];
#pragma unroll
    for (int j = 0; j < HIDD; j++)
        pj[j] = y0 * __ldg(&w1[j * DM + t]) + y1 * __ldg(&w1[j * DM + t + 256]);
#pragma unroll
    for (int j = 0; j < HIDD; j++)
#pragma unroll
        for (int o = 16; o > 0; o >>= 1)
            pj[j] += __shfl_down_sync(0xffffffffu, pj[j], o);

    __shared__ float hred[8][HIDD];
    if (lane == 0)
#pragma unroll
        for (int j = 0; j < HIDD; j++) hred[warp][j] = pj[j];
    __syncthreads();

    __shared__ float sh[HIDD];
    if (t < HIDD) {
        float hv = b1[t];
#pragma unroll
        for (int w = 0; w < 8; w++) hv += hred[w][t];
        sh[t] = fmaxf(hv, 0.f);
    }
    __syncthreads();

    float o0 = b2[t], o1 = b2[t + 256];
#pragma unroll
    for (int j = 0; j < HIDD; j++) {
        const float hj = sh[j];
        o0 = fmaf(hj, __ldg(&w2[t * HIDD + j]), o0);
        o1 = fmaf(hj, __ldg(&w2[(t + 256) * HIDD + j]), o1);
    }
    out[row * DM + t] = o0;
    out[row * DM + t + 256] = o1;
}

// ---------------- launch ----------------
extern "C" void kernel_launch(void* const* d_in, const int* in_sizes, int n_in,
                              void* d_out, int out_size)
{
    const float* x   = (const float*)d_in[0];
    const float* xe  = (const float*)d_in[1];
    const float* Wq  = (const float*)d_in[2];
    const float* Wk  = (const float*)d_in[3];
    const float* Wv  = (const float*)d_in[4];
    const float* lg  = (const float*)d_in[5];
    const float* lb  = (const float*)d_in[6];
    const float* w1  = (const float*)d_in[7];
    const float* b1  = (const float*)d_in[8];
    const float* w2  = (const float*)d_in[9];
    const float* b2  = (const float*)d_in[10];
    float* out = (float*)d_out;

    float *qkv, *kvenc, *q2, *fx, *fx2;
    cudaGetSymbolAddress((void**)&qkv,   g_qkv);
    cudaGetSymbolAddress((void**)&kvenc, g_kvenc);
    cudaGetSymbolAddress((void**)&q2,    g_q2);
    cudaGetSymbolAddress((void**)&fx,    g_fx);
    cudaGetSymbolAddress((void**)&fx2,   g_fx2);

    // projections for self-attention: [Q|K|V] into g_qkv (ldc = 1024)
    sgemm_k<<<dim3(2, 32), 256>>>(x, 512, Wq, 256, qkv + 0,   1024, 512);
    sgemm_k<<<dim3(2, 32), 256>>>(x, 512, Wk, 256, qkv + 256, 1024, 512);
    sgemm_k<<<dim3(4, 32), 256>>>(x, 512, Wv, 512, qkv + 512, 1024, 512);
    // encoder K,V into g_kvenc (ldc = 768)
    sgemm_k<<<dim3(2, 32), 256>>>(xe, 512, Wk, 256, kvenc + 0,   768, 512);
    sgemm_k<<<dim3(4, 32), 256>>>(xe, 512, Wv, 512, kvenc + 256, 768, 512);

    // self-attention (multiplicative causal mask quirk)
    attn_k<1><<<512, 512>>>(qkv, 1024, 0, qkv, 1024, 256, 512, fx);

    // cross-attention Q projection from fx
    sgemm_k<<<dim3(2, 32), 256>>>(fx, 512, Wq, 256, q2, 256, 512);

    // cross-attention (no mask)
    attn_k<0><<<512, 512>>>(q2, 256, 0, kvenc, 768, 0, 256, fx2);

    // residual + LN + FFN
    lnffn_k<<<4096, 256>>>(x, fx2, lg, lb, w1, b1, w2, b2, out);
}

// round 2
// speedup vs baseline: 1.4827x; 1.4827x over previous
#include <cuda_runtime.h>
#include <cuda_bf16.h>

#define BS 8
#define SEQ 512
#define DM 512
#define NROW (BS*SEQ)          // 4096

// ---------------- scratch (no allocation allowed) ----------------
__device__ float g_qkv[NROW * 1024];   // [Q(256) | K(256) | V(512)] self
__device__ float g_kvenc[NROW * 768];  // [K(256) | V(512)] encoder
__device__ float g_q2[NROW * 256];     // Q of cross attention
__device__ float g_fx[NROW * 512];     // self-attn output
__device__ float g_fx2[NROW * 512];    // cross-attn output
__device__ float g_W[512 * 1024];      // packed [Wq|Wk|Wv]

// ---------------- f32x2 helpers ----------------
__device__ __forceinline__ unsigned long long pk2(float x, float y) {
    unsigned long long r;
    asm("mov.b64 %0, {%1,%2};" : "=l"(r) : "f"(x), "f"(y));
    return r;
}
__device__ __forceinline__ void fma2(unsigned long long& d, unsigned long long a, unsigned long long b) {
    asm("fma.rn.f32x2 %0, %1, %2, %0;" : "+l"(d) : "l"(a), "l"(b));
}
__device__ __forceinline__ float2 up2(unsigned long long v) {
    float2 r;
    asm("mov.b64 {%0,%1}, %2;" : "=f"(r.x), "=f"(r.y) : "l"(v));
    return r;
}
__device__ __forceinline__ float ex2(float x) {
    float y;
    asm("ex2.approx.f32 %0, %1;" : "=f"(y) : "f"(x));
    return y;
}

// ---------------- weight packing: g_W = [Wq | Wk | Wv] (512 x 1024) ----------------
__global__ __launch_bounds__(256) void packW_k(const float4* __restrict__ Wq,
                                               const float4* __restrict__ Wk,
                                               const float4* __restrict__ Wv,
                                               float4* __restrict__ W)
{
    int i = blockIdx.x * 256 + threadIdx.x;   // 512*256 float4s
    int r = i >> 8, c = i & 255;
    float4 v;
    if (c < 64)       v = Wq[r * 64 + c];
    else if (c < 128) v = Wk[r * 64 + (c - 64)];
    else              v = Wv[r * 128 + (c - 128)];
    W[i] = v;
}

// ---------------- FFMA2 SGEMM body: 128x128 tile, BK=8 ----------------
struct SmemG {
    unsigned long long As2[8][128];  // A values pre-packed as (a,a) pairs
    float Bs[8][128];
};

__device__ __forceinline__ void gemm_body(SmemG& sm,
    const float* __restrict__ A, int lda,
    const float* __restrict__ B, int ldb,
    float* __restrict__ C, int ldc, int K, int bx, int by)
{
    const int tid = threadIdx.x;
    A += by * 128 * lda;
    B += bx * 128;
    C += by * 128 * ldc + bx * 128;

    const int aRow = tid >> 1, aCol = (tid & 1) << 2;
    const int bRow = tid >> 5, bCol = (tid & 31) << 2;
    const int tr = (tid >> 4) * 8, tc = (tid & 15) * 8;

    unsigned long long acc[8][4];
#pragma unroll
    for (int i = 0; i < 8; i++)
#pragma unroll
        for (int j = 0; j < 4; j++) acc[i][j] = 0ULL;

    for (int k0 = 0; k0 < K; k0 += 8) {
        float4 a = *(const float4*)(A + aRow * lda + k0 + aCol);
        sm.As2[aCol + 0][aRow] = pk2(a.x, a.x);
        sm.As2[aCol + 1][aRow] = pk2(a.y, a.y);
        sm.As2[aCol + 2][aRow] = pk2(a.z, a.z);
        sm.As2[aCol + 3][aRow] = pk2(a.w, a.w);
        *(float4*)&sm.Bs[bRow][bCol] = *(const float4*)(B + (k0 + bRow) * ldb + bCol);
        __syncthreads();

#pragma unroll
        for (int k = 0; k < 8; k++) {
            ulonglong2 am0 = *(const ulonglong2*)&sm.As2[k][tr];
            ulonglong2 am1 = *(const ulonglong2*)&sm.As2[k][tr + 2];
            ulonglong2 am2 = *(const ulonglong2*)&sm.As2[k][tr + 4];
            ulonglong2 am3 = *(const ulonglong2*)&sm.As2[k][tr + 6];
            ulonglong2 b0 = *(const ulonglong2*)&sm.Bs[k][tc];
            ulonglong2 b1 = *(const ulonglong2*)&sm.Bs[k][tc + 4];
            unsigned long long am[8] = {am0.x, am0.y, am1.x, am1.y, am2.x, am2.y, am3.x, am3.y};
            unsigned long long bn[4] = {b0.x, b0.y, b1.x, b1.y};
#pragma unroll
            for (int i = 0; i < 8; i++)
#pragma unroll
                for (int j = 0; j < 4; j++)
                    fma2(acc[i][j], am[i], bn[j]);
        }
        __syncthreads();
    }

#pragma unroll
    for (int i = 0; i < 8; i++) {
        ulonglong2 s0, s1;
        s0.x = acc[i][0]; s0.y = acc[i][1];
        s1.x = acc[i][2]; s1.y = acc[i][3];
        *(ulonglong2*)(C + (tr + i) * ldc + tc) = s0;
        *(ulonglong2*)(C + (tr + i) * ldc + tc + 4) = s1;
    }
}

// fused projections: z=0 -> self QKV (N=1024), z=1 -> encoder KV (N=768)
__global__ __launch_bounds__(256, 2) void proj_k(
    const float* __restrict__ x, const float* __restrict__ xe,
    const float* __restrict__ W, float* __restrict__ qkv, float* __restrict__ kvenc)
{
    __shared__ SmemG sm;
    if (blockIdx.z == 0) {
        gemm_body(sm, x, 512, W, 1024, qkv, 1024, 512, blockIdx.x, blockIdx.y);
    } else {
        if (blockIdx.x >= 6) return;
        gemm_body(sm, xe, 512, W + 256, 1024, kvenc, 768, 512, blockIdx.x, blockIdx.y);
    }
}

__global__ __launch_bounds__(256, 2) void sgemm2_k(
    const float* __restrict__ A, int lda, const float* __restrict__ B, int ldb,
    float* __restrict__ C, int ldc, int K)
{
    __shared__ SmemG sm;
    gemm_body(sm, A, lda, B, ldb, C, ldc, K, blockIdx.x, blockIdx.y);
}

// ---------------- Attention (FFMA2, base-2 softmax, causal suffix trick) ----------------
// Scores pre-scaled by (1/sqrt(DK))*log2(e) so softmax == exp2-based; exactly
// equivalent math to reference (shift-invariant). Causal quirk: masked score==0
// participates in softmax -> masked weight = ex2(0-m) const; masked V-sum via
// suffix sums computed with a warp shfl scan.
template <int CAUSAL>
__global__ __launch_bounds__(512, 2) void attn2_k(
    const float* __restrict__ Qbuf, int ldq, int qoff,
    const float* __restrict__ KVbuf, int ldkv, int koff, int voff,
    float* __restrict__ Out)
{
    __shared__ float sKt[4][512];                 // K transposed: [dim][key]
    __shared__ __align__(16) float sV[512 * 8];   // V row-major:  [key][dim]
    __shared__ float sWS[16][8];                  // warp V-sums for suffix scan

    const int bh = blockIdx.x;
    const int h = bh & 63, b = bh >> 6;
    const int t = threadIdx.x, lane = t & 31, wid = t >> 5;
    const int rowbase = b * SEQ + t;

    const float* kv = KVbuf + rowbase * ldkv;
    float4 kk = *(const float4*)(kv + koff + h * 4);
    sKt[0][t] = kk.x; sKt[1][t] = kk.y; sKt[2][t] = kk.z; sKt[3][t] = kk.w;
    float4 v0 = *(const float4*)(kv + voff + h * 8);
    float4 v1 = *(const float4*)(kv + voff + h * 8 + 4);
    *(float4*)&sV[t * 8] = v0;
    *(float4*)&sV[t * 8 + 4] = v1;

    float vown[8] = {v0.x, v0.y, v0.z, v0.w, v1.x, v1.y, v1.z, v1.w};
    float suf[8];
    if (CAUSAL) {
#pragma unroll
        for (int d = 0; d < 8; d++) suf[d] = vown[d];
#pragma unroll
        for (int off = 1; off < 32; off <<= 1) {
#pragma unroll
            for (int d = 0; d < 8; d++) {
                float o = __shfl_down_sync(0xffffffffu, suf[d], off);
                if (lane + off < 32) suf[d] += o;
            }
        }
        if (lane == 0) {
#pragma unroll
            for (int d = 0; d < 8; d++) sWS[wid][d] = suf[d];
        }
    }
    __syncthreads();
    if (CAUSAL) {
        for (int w = wid + 1; w < 16; w++)
#pragma unroll
            for (int d = 0; d < 8; d++) suf[d] += sWS[w][d];
        // suf = sum_{k >= t}; want sum_{k > t}:
#pragma unroll
        for (int d = 0; d < 8; d++) suf[d] -= vown[d];
    }

    const int q = t;
    const float SCQ = 0.72134752044448170f;  // 0.5 * log2(e)
    float4 qv = *(const float4*)(Qbuf + rowbase * ldq + qoff + h * 4);
    const float qs0 = qv.x * SCQ, qs1 = qv.y * SCQ, qs2 = qv.z * SCQ, qs3 = qv.w * SCQ;
    unsigned long long aq0 = pk2(qs0, qs0), aq1 = pk2(qs1, qs1);
    unsigned long long aq2 = pk2(qs2, qs2), aq3 = pk2(qs3, qs3);

    const int n = CAUSAL ? (q + 1) : SEQ;
    const int nquad = n >> 2;

    // pass 1: max (causal includes implicit 0 from masked scores)
    float m = CAUSAL ? 0.f : -3.0e38f;
    for (int i = 0; i < nquad; i++) {
        const int k4 = i << 2;
        ulonglong2 k0 = *(const ulonglong2*)&sKt[0][k4];
        ulonglong2 k1 = *(const ulonglong2*)&sKt[1][k4];
        ulonglong2 k2 = *(const ulonglong2*)&sKt[2][k4];
        ulonglong2 k3 = *(const ulonglong2*)&sKt[3][k4];
        unsigned long long s01 = 0ULL, s23 = 0ULL;
        fma2(s01, aq0, k0.x); fma2(s23, aq0, k0.y);
        fma2(s01, aq1, k1.x); fma2(s23, aq1, k1.y);
        fma2(s01, aq2, k2.x); fma2(s23, aq2, k2.y);
        fma2(s01, aq3, k3.x); fma2(s23, aq3, k3.y);
        float2 f01 = up2(s01), f23 = up2(s23);
        m = fmaxf(m, fmaxf(fmaxf(f01.x, f01.y), fmaxf(f23.x, f23.y)));
    }
    for (int k = nquad << 2; k < n; k++) {
        float s = fmaf(qs0, sKt[0][k], fmaf(qs1, sKt[1][k], fmaf(qs2, sKt[2][k], qs3 * sKt[3][k])));
        m = fmaxf(m, s);
    }

    // pass 2: denom + weighted V
    const unsigned long long nm = pk2(-m, -m);
    float denom = 0.f;
    unsigned long long acc0 = 0, acc1 = 0, acc2 = 0, acc3 = 0;
    for (int i = 0; i < nquad; i++) {
        const int k4 = i << 2;
        ulonglong2 k0 = *(const ulonglong2*)&sKt[0][k4];
        ulonglong2 k1 = *(const ulonglong2*)&sKt[1][k4];
        ulonglong2 k2 = *(const ulonglong2*)&sKt[2][k4];
        ulonglong2 k3 = *(const ulonglong2*)&sKt[3][k4];
        unsigned long long s01 = nm, s23 = nm;
        fma2(s01, aq0, k0.x); fma2(s23, aq0, k0.y);
        fma2(s01, aq1, k1.x); fma2(s23, aq1, k1.y);
        fma2(s01, aq2, k2.x); fma2(s23, aq2, k2.y);
        fma2(s01, aq3, k3.x); fma2(s23, aq3, k3.y);
        float2 f01 = up2(s01), f23 = up2(s23);
        float p0 = ex2(f01.x), p1 = ex2(f01.y), p2 = ex2(f23.x), p3 = ex2(f23.y);
        denom += (p0 + p1) + (p2 + p3);
        const float* vb = &sV[k4 * 8];
        {
            unsigned long long P = pk2(p0, p0);
            ulonglong2 va = *(const ulonglong2*)(vb);
            ulonglong2 vc = *(const ulonglong2*)(vb + 4);
            fma2(acc0, P, va.x); fma2(acc1, P, va.y); fma2(acc2, P, vc.x); fma2(acc3, P, vc.y);
        }
        {
            unsigned long long P = pk2(p1, p1);
            ulonglong2 va = *(const ulonglong2*)(vb + 8);
            ulonglong2 vc = *(const ulonglong2*)(vb + 12);
            fma2(acc0, P, va.x); fma2(acc1, P, va.y); fma2(acc2, P, vc.x); fma2(acc3, P, vc.y);
        }
        {
            unsigned long long P = pk2(p2, p2);
            ulonglong2 va = *(const ulonglong2*)(vb + 16);
            ulonglong2 vc = *(const ulonglong2*)(vb + 20);
            fma2(acc0, P, va.x); fma2(acc1, P, va.y); fma2(acc2, P, vc.x); fma2(acc3, P, vc.y);
        }
        {
            unsigned long long P = pk2(p3, p3);
            ulonglong2 va = *(const ulonglong2*)(vb + 24);
            ulonglong2 vc = *(const ulonglong2*)(vb + 28);
            fma2(acc0, P, va.x); fma2(acc1, P, va.y); fma2(acc2, P, vc.x); fma2(acc3, P, vc.y);
        }
    }
    for (int k = nquad << 2; k < n; k++) {
        float s = -m + fmaf(qs0, sKt[0][k], fmaf(qs1, sKt[1][k], fmaf(qs2, sKt[2][k], qs3 * sKt[3][k])));
        float p = ex2(s);
        denom += p;
        unsigned long long P = pk2(p, p);
        const float* vb = &sV[k * 8];
        ulonglong2 va = *(const ulonglong2*)(vb);
        ulonglong2 vc = *(const ulonglong2*)(vb + 4);
        fma2(acc0, P, va.x); fma2(acc1, P, va.y); fma2(acc2, P, vc.x); fma2(acc3, P, vc.y);
    }

    if (CAUSAL) {
        float pm = ex2(-m);                       // weight of each masked key
        denom += (float)(SEQ - 1 - q) * pm;
        unsigned long long P = pk2(pm, pm);
        unsigned long long sp0 = pk2(suf[0], suf[1]);
        unsigned long long sp1 = pk2(suf[2], suf[3]);
        unsigned long long sp2 = pk2(suf[4], suf[5]);
        unsigned long long sp3 = pk2(suf[6], suf[7]);
        fma2(acc0, P, sp0); fma2(acc1, P, sp1); fma2(acc2, P, sp2); fma2(acc3, P, sp3);
    }

    const float inv = 1.0f / denom;
    float2 o0 = up2(acc0), o1 = up2(acc1), o2 = up2(acc2), o3 = up2(acc3);
    float* o = Out + rowbase * DM + h * 8;
    *(float4*)(o)     = make_float4(o0.x * inv, o0.y * inv, o1.x * inv, o1.y * inv);
    *(float4*)(o + 4) = make_float4(o2.x * inv, o2.y * inv, o3.x * inv, o3.y * inv);
}

// ---------------- Residual + LayerNorm + FFN (hidden=10) fused ----------------
#define HIDD 10
__global__ __launch_bounds__(256) void lnffn_k(
    const float* __restrict__ x, const float* __restrict__ fx,
    const float* __restrict__ lg, const float* __restrict__ lb,
    const float* __restrict__ w1, const float* __restrict__ b1,
    const float* __restrict__ w2, const float* __restrict__ b2,
    float* __restrict__ out)
{
    const int row = blockIdx.x;
    const int t = threadIdx.x;
    const int warp = t >> 5, lane = t & 31;

    const float* xr = x + row * DM;
    const float* fr = fx + row * DM;
    float v0 = xr[t] + fr[t];
    float v1 = xr[t + 256] + fr[t + 256];

    float s = v0 + v1;
    float ss = v0 * v0 + v1 * v1;
#pragma unroll
    for (int o = 16; o > 0; o >>= 1) {
        s  += __shfl_down_sync(0xffffffffu, s,  o);
        ss += __shfl_down_sync(0xffffffffu, ss, o);
    }
    __shared__ float rs[8], rss[8];
    if (lane == 0) { rs[warp] = s; rss[warp] = ss; }
    __syncthreads();
    float S = 0.f, SS = 0.f;
#pragma unroll
    for (int w = 0; w < 8; w++) { S += rs[w]; SS += rss[w]; }
    const float mu = S * (1.0f / DM);
    const float var = SS * (1.0f / DM) - mu * mu;
    const float rstd = rsqrtf(var + 1e-5f);

    const float y0 = (v0 - mu) * rstd * lg[t] + lb[t];
    const float y1 = (v1 - mu) * rstd * lg[t + 256] + lb[t + 256];

    float pj[HIDD];
#pragma unroll
    for (int j = 0; j < HIDD; j++)
        pj[j] = y0 * __ldg(&w1[j * DM + t]) + y1 * __ldg(&w1[j * DM + t + 256]);
#pragma unroll
    for (int j = 0; j < HIDD; j++)
#pragma unroll
        for (int o = 16; o > 0; o >>= 1)
            pj[j] += __shfl_down_sync(0xffffffffu, pj[j], o);

    __shared__ float hred[8][HIDD];
    if (lane == 0)
#pragma unroll
        for (int j = 0; j < HIDD; j++) hred[warp][j] = pj[j];
    __syncthreads();

    __shared__ float sh[HIDD];
    if (t < HIDD) {
        float hv = b1[t];
#pragma unroll
        for (int w = 0; w < 8; w++) hv += hred[w][t];
        sh[t] = fmaxf(hv, 0.f);
    }
    __syncthreads();

    float o0 = b2[t], o1 = b2[t + 256];
#pragma unroll
    for (int j = 0; j < HIDD; j++) {
        const float hj = sh[j];
        o0 = fmaf(hj, __ldg(&w2[t * HIDD + j]), o0);
        o1 = fmaf(hj, __ldg(&w2[(t + 256) * HIDD + j]), o1);
    }
    out[row * DM + t] = o0;
    out[row * DM + t + 256] = o1;
}

// ---------------- launch ----------------
extern "C" void kernel_launch(void* const* d_in, const int* in_sizes, int n_in,
                              void* d_out, int out_size)
{
    const float* x   = (const float*)d_in[0];
    const float* xe  = (const float*)d_in[1];
    const float* Wq  = (const float*)d_in[2];
    const float* Wk  = (const float*)d_in[3];
    const float* Wv  = (const float*)d_in[4];
    const float* lg  = (const float*)d_in[5];
    const float* lb  = (const float*)d_in[6];
    const float* w1  = (const float*)d_in[7];
    const float* b1  = (const float*)d_in[8];
    const float* w2  = (const float*)d_in[9];
    const float* b2  = (const float*)d_in[10];
    float* out = (float*)d_out;

    float *qkv, *kvenc, *q2, *fx, *fx2, *W;
    cudaGetSymbolAddress((void**)&qkv,   g_qkv);
    cudaGetSymbolAddress((void**)&kvenc, g_kvenc);
    cudaGetSymbolAddress((void**)&q2,    g_q2);
    cudaGetSymbolAddress((void**)&fx,    g_fx);
    cudaGetSymbolAddress((void**)&fx2,   g_fx2);
    cudaGetSymbolAddress((void**)&W,     g_W);

    // pack weights [Wq|Wk|Wv]
    packW_k<<<512, 256>>>((const float4*)Wq, (const float4*)Wk, (const float4*)Wv, (float4*)W);

    // fused projections: self QKV + encoder KV in one launch (448 working blocks)
    proj_k<<<dim3(8, 32, 2), 256>>>(x, xe, W, qkv, kvenc);

    // self-attention (multiplicative causal mask quirk + suffix-sum fast path)
    attn2_k<1><<<512, 512>>>(qkv, 1024, 0, qkv, 1024, 256, 512, fx);

    // cross-attention Q projection from fx
    sgemm2_k<<<dim3(2, 32), 256>>>(fx, 512, Wq, 256, q2, 256, 512);

    // cross-attention (no mask)
    attn2_k<0><<<512, 512>>>(q2, 256, 0, kvenc, 768, 0, 256, fx2);

    // residual + LN + FFN
    lnffn_k<<<4096, 256>>>(x, fx2, lg, lb, w1, b1, w2, b2, out);
}

// round 3
// speedup vs baseline: 1.6079x; 1.0844x over previous
#include <cuda_runtime.h>
#include <cuda_bf16.h>

#define BS 8
#define SEQ 512
#define DM 512
#define NROW (BS*SEQ)          // 4096

// ---------------- scratch (no allocation allowed) ----------------
__device__ float g_qkv[NROW * 1024];   // [Q(256) | K(256) | V(512)] self
__device__ float g_kvenc[NROW * 768];  // [K(256) | V(512)] encoder
__device__ float g_q2a[NROW * 256];    // cross-Q split-K partial 0
__device__ float g_q2b[NROW * 256];    // cross-Q split-K partial 1
__device__ float g_fx[NROW * 512];     // self-attn output
__device__ float g_fx2[NROW * 512];    // cross-attn output
__device__ float g_W[512 * 1024];      // packed [Wq|Wk|Wv]

// ---------------- f32x2 helpers ----------------
__device__ __forceinline__ unsigned long long pk2(float x, float y) {
    unsigned long long r;
    asm("mov.b64 %0, {%1,%2};" : "=l"(r) : "f"(x), "f"(y));
    return r;
}
__device__ __forceinline__ void fma2(unsigned long long& d, unsigned long long a, unsigned long long b) {
    asm("fma.rn.f32x2 %0, %1, %2, %0;" : "+l"(d) : "l"(a), "l"(b));
}
__device__ __forceinline__ float2 up2(unsigned long long v) {
    float2 r;
    asm("mov.b64 {%0,%1}, %2;" : "=f"(r.x), "=f"(r.y) : "l"(v));
    return r;
}
__device__ __forceinline__ float ex2(float x) {
    float y;
    asm("ex2.approx.f32 %0, %1;" : "=f"(y) : "f"(x));
    return y;
}

// ---------------- weight packing: g_W = [Wq | Wk | Wv] (512 x 1024) ----------------
__global__ __launch_bounds__(256) void packW_k(const float4* __restrict__ Wq,
                                               const float4* __restrict__ Wk,
                                               const float4* __restrict__ Wv,
                                               float4* __restrict__ W)
{
    int i = blockIdx.x * 256 + threadIdx.x;   // 512*256 float4s
    int r = i >> 8, c = i & 255;
    float4 v;
    if (c < 64)       v = Wq[r * 64 + c];
    else if (c < 128) v = Wk[r * 64 + (c - 64)];
    else              v = Wv[r * 128 + (c - 128)];
    W[i] = v;
}

// ============ double-buffered FFMA2 GEMM body: 128x64 tile, BK=8 ============
// A,B,C already offset to the tile. 256 threads. NTILES = K/8.
__device__ __forceinline__ void gemm128x64(
    const float* __restrict__ A, int lda,
    const float* __restrict__ B, int ldb,
    float* __restrict__ C, int ldc, int ntiles,
    unsigned long long (*As)[8][128], float (*Bs)[8][64])
{
    const int tid  = threadIdx.x;
    const int aRow = tid >> 1, aCol = (tid & 1) << 2;   // float4 of A
    const int bRow = tid >> 5, bCol = (tid & 31) << 1;  // float2 of B
    const int tr = (tid >> 4) << 3, tc = (tid & 15) << 2;

    // preload tile 0
    {
        float4 a = *(const float4*)(A + aRow * lda + aCol);
        float2 b = *(const float2*)(B + bRow * ldb + bCol);
        As[0][aCol + 0][aRow] = pk2(a.x, a.x);
        As[0][aCol + 1][aRow] = pk2(a.y, a.y);
        As[0][aCol + 2][aRow] = pk2(a.z, a.z);
        As[0][aCol + 3][aRow] = pk2(a.w, a.w);
        Bs[0][bRow][bCol] = b.x; Bs[0][bRow][bCol + 1] = b.y;
    }
    __syncthreads();

    unsigned long long acc[8][2];
#pragma unroll
    for (int i = 0; i < 8; i++) { acc[i][0] = 0ULL; acc[i][1] = 0ULL; }

    for (int t = 0; t < ntiles; t++) {
        const int cur = t & 1;
        float4 an; float2 bn;
        const bool more = (t + 1 < ntiles);
        if (more) {
            an = *(const float4*)(A + aRow * lda + (t + 1) * 8 + aCol);
            bn = *(const float2*)(B + ((t + 1) * 8 + bRow) * ldb + bCol);
        }
#pragma unroll
        for (int k = 0; k < 8; k++) {
            ulonglong2 a0 = *(const ulonglong2*)&As[cur][k][tr];
            ulonglong2 a1 = *(const ulonglong2*)&As[cur][k][tr + 2];
            ulonglong2 a2 = *(const ulonglong2*)&As[cur][k][tr + 4];
            ulonglong2 a3 = *(const ulonglong2*)&As[cur][k][tr + 6];
            ulonglong2 bb = *(const ulonglong2*)&Bs[cur][k][tc];   // float4 == 2 x f32x2
            unsigned long long am[8] = {a0.x, a0.y, a1.x, a1.y, a2.x, a2.y, a3.x, a3.y};
#pragma unroll
            for (int i = 0; i < 8; i++) {
                fma2(acc[i][0], am[i], bb.x);
                fma2(acc[i][1], am[i], bb.y);
            }
        }
        if (more) {
            const int nxt = cur ^ 1;
            As[nxt][aCol + 0][aRow] = pk2(an.x, an.x);
            As[nxt][aCol + 1][aRow] = pk2(an.y, an.y);
            As[nxt][aCol + 2][aRow] = pk2(an.z, an.z);
            As[nxt][aCol + 3][aRow] = pk2(an.w, an.w);
            Bs[nxt][bRow][bCol] = bn.x; Bs[nxt][bRow][bCol + 1] = bn.y;
            __syncthreads();
        }
    }

#pragma unroll
    for (int i = 0; i < 8; i++) {
        ulonglong2 s;
        s.x = acc[i][0]; s.y = acc[i][1];
        *(ulonglong2*)(C + (tr + i) * ldc + tc) = s;
    }
}

// fused projections, flattened grid of 896 blocks:
//   bid <  512 : self QKV  (32 m-tiles x 16 n-tiles), C = qkv (ldc 1024)
//   bid >= 512 : enc  KV   (32 m-tiles x 12 n-tiles), C = kvenc (ldc 768)
__global__ __launch_bounds__(256, 2) void proj_k(
    const float* __restrict__ x, const float* __restrict__ xe,
    const float* __restrict__ W, float* __restrict__ qkv, float* __restrict__ kvenc)
{
    __shared__ __align__(16) unsigned long long As[2][8][128];
    __shared__ __align__(16) float Bs[2][8][64];

    const int bid = blockIdx.x;
    if (bid < 512) {
        const int bx = bid & 15, by = bid >> 4;
        gemm128x64(x + by * 128 * 512, 512,
                   W + bx * 64, 1024,
                   qkv + by * 128 * 1024 + bx * 64, 1024, 64, As, Bs);
    } else {
        const int i = bid - 512;
        const int bx = i % 12, by = i / 12;
        gemm128x64(xe + by * 128 * 512, 512,
                   W + 256 + bx * 64, 1024,
                   kvenc + by * 128 * 768 + bx * 64, 768, 64, As, Bs);
    }
}

// ============ cross-Q GEMM: 64x64 tile, split-K=2, double-buffered ============
// grid (4, 64, 2): x = n-tile, y = m-tile, z = K-half. Partials to q2a/q2b.
__global__ __launch_bounds__(256, 2) void crossq_k(
    const float* __restrict__ fx, const float* __restrict__ Wq,
    float* __restrict__ q2a, float* __restrict__ q2b)
{
    __shared__ __align__(16) unsigned long long As[2][8][64];
    __shared__ __align__(16) float Bs[2][8][64];

    const int tid  = threadIdx.x;
    const int aRow = tid >> 2, aCol = (tid & 3) << 1;   // float2 of A (64x8)
    const int bRow = tid >> 5, bCol = (tid & 31) << 1;  // float2 of B (8x64)
    const int tr = (tid >> 4) << 2, tc = (tid & 15) << 2;

    const int kz = blockIdx.z;
    const float* A = fx + blockIdx.y * 64 * 512 + kz * 256;          // lda 512
    const float* B = Wq + kz * 256 * 256 + blockIdx.x * 64;          // ldb 256
    float* C = (kz ? q2b : q2a) + blockIdx.y * 64 * 256 + blockIdx.x * 64;

    {
        float2 a = *(const float2*)(A + aRow * 512 + aCol);
        float2 b = *(const float2*)(B + bRow * 256 + bCol);
        As[0][aCol + 0][aRow] = pk2(a.x, a.x);
        As[0][aCol + 1][aRow] = pk2(a.y, a.y);
        Bs[0][bRow][bCol] = b.x; Bs[0][bRow][bCol + 1] = b.y;
    }
    __syncthreads();

    unsigned long long acc[4][2];
#pragma unroll
    for (int i = 0; i < 4; i++) { acc[i][0] = 0ULL; acc[i][1] = 0ULL; }

    const int NT = 32;  // 256 / 8
    for (int t = 0; t < NT; t++) {
        const int cur = t & 1;
        float2 an, bn;
        const bool more = (t + 1 < NT);
        if (more) {
            an = *(const float2*)(A + aRow * 512 + (t + 1) * 8 + aCol);
            bn = *(const float2*)(B + ((t + 1) * 8 + bRow) * 256 + bCol);
        }
#pragma unroll
        for (int k = 0; k < 8; k++) {
            ulonglong2 a0 = *(const ulonglong2*)&As[cur][k][tr];
            ulonglong2 a1 = *(const ulonglong2*)&As[cur][k][tr + 2];
            ulonglong2 bb = *(const ulonglong2*)&Bs[cur][k][tc];
            unsigned long long am[4] = {a0.x, a0.y, a1.x, a1.y};
#pragma unroll
            for (int i = 0; i < 4; i++) {
                fma2(acc[i][0], am[i], bb.x);
                fma2(acc[i][1], am[i], bb.y);
            }
        }
        if (more) {
            const int nxt = cur ^ 1;
            As[nxt][aCol + 0][aRow] = pk2(an.x, an.x);
            As[nxt][aCol + 1][aRow] = pk2(an.y, an.y);
            Bs[nxt][bRow][bCol] = bn.x; Bs[nxt][bRow][bCol + 1] = bn.y;
            __syncthreads();
        }
    }

#pragma unroll
    for (int i = 0; i < 4; i++) {
        ulonglong2 s;
        s.x = acc[i][0]; s.y = acc[i][1];
        *(ulonglong2*)(C + (tr + i) * 256 + tc) = s;
    }
}

// ---------------- Attention (FFMA2, base-2 softmax, causal suffix trick) ----------------
// QSUM: Q = Qbuf + Qbuf2 (split-K partial sum folded into the load).
template <int CAUSAL, int QSUM>
__global__ __launch_bounds__(512, 2) void attn2_k(
    const float* __restrict__ Qbuf, const float* __restrict__ Qbuf2, int ldq, int qoff,
    const float* __restrict__ KVbuf, int ldkv, int koff, int voff,
    float* __restrict__ Out)
{
    __shared__ float sKt[4][512];                 // K transposed: [dim][key]
    __shared__ __align__(16) float sV[512 * 8];   // V row-major:  [key][dim]
    __shared__ float sWS[16][8];                  // warp V-sums for suffix scan

    const int bh = blockIdx.x;
    const int h = bh & 63, b = bh >> 6;
    const int t = threadIdx.x, lane = t & 31, wid = t >> 5;
    const int rowbase = b * SEQ + t;

    const float* kv = KVbuf + rowbase * ldkv;
    float4 kk = *(const float4*)(kv + koff + h * 4);
    sKt[0][t] = kk.x; sKt[1][t] = kk.y; sKt[2][t] = kk.z; sKt[3][t] = kk.w;
    float4 v0 = *(const float4*)(kv + voff + h * 8);
    float4 v1 = *(const float4*)(kv + voff + h * 8 + 4);
    *(float4*)&sV[t * 8] = v0;
    *(float4*)&sV[t * 8 + 4] = v1;

    float suf[8];
    if (CAUSAL) {
        float vown[8] = {v0.x, v0.y, v0.z, v0.w, v1.x, v1.y, v1.z, v1.w};
#pragma unroll
        for (int d = 0; d < 8; d++) suf[d] = vown[d];
#pragma unroll
        for (int off = 1; off < 32; off <<= 1) {
#pragma unroll
            for (int d = 0; d < 8; d++) {
                float o = __shfl_down_sync(0xffffffffu, suf[d], off);
                if (lane + off < 32) suf[d] += o;
            }
        }
        if (lane == 0) {
#pragma unroll
            for (int d = 0; d < 8; d++) sWS[wid][d] = suf[d];
        }
        __syncthreads();
        for (int w = wid + 1; w < 16; w++)
#pragma unroll
            for (int d = 0; d < 8; d++) suf[d] += sWS[w][d];
#pragma unroll
        for (int d = 0; d < 8; d++) suf[d] -= vown[d];   // sum_{k > t}
    } else {
        __syncthreads();
    }

    const int q = t;
    const float SCQ = 0.72134752044448170f;  // 0.5 * log2(e)
    float4 qv = *(const float4*)(Qbuf + rowbase * ldq + qoff + h * 4);
    if (QSUM) {
        float4 qv2 = *(const float4*)(Qbuf2 + rowbase * ldq + qoff + h * 4);
        qv.x += qv2.x; qv.y += qv2.y; qv.z += qv2.z; qv.w += qv2.w;
    }
    const float qs0 = qv.x * SCQ, qs1 = qv.y * SCQ, qs2 = qv.z * SCQ, qs3 = qv.w * SCQ;
    unsigned long long aq0 = pk2(qs0, qs0), aq1 = pk2(qs1, qs1);
    unsigned long long aq2 = pk2(qs2, qs2), aq3 = pk2(qs3, qs3);

    const int n = CAUSAL ? (q + 1) : SEQ;
    const int nquad = n >> 2;

    // pass 1: max (causal includes implicit 0 from masked scores)
    float m = CAUSAL ? 0.f : -3.0e38f;
    for (int i = 0; i < nquad; i++) {
        const int k4 = i << 2;
        ulonglong2 k0 = *(const ulonglong2*)&sKt[0][k4];
        ulonglong2 k1 = *(const ulonglong2*)&sKt[1][k4];
        ulonglong2 k2 = *(const ulonglong2*)&sKt[2][k4];
        ulonglong2 k3 = *(const ulonglong2*)&sKt[3][k4];
        unsigned long long s01 = 0ULL, s23 = 0ULL;
        fma2(s01, aq0, k0.x); fma2(s23, aq0, k0.y);
        fma2(s01, aq1, k1.x); fma2(s23, aq1, k1.y);
        fma2(s01, aq2, k2.x); fma2(s23, aq2, k2.y);
        fma2(s01, aq3, k3.x); fma2(s23, aq3, k3.y);
        float2 f01 = up2(s01), f23 = up2(s23);
        m = fmaxf(m, fmaxf(fmaxf(f01.x, f01.y), fmaxf(f23.x, f23.y)));
    }
    for (int k = nquad << 2; k < n; k++) {
        float s = fmaf(qs0, sKt[0][k], fmaf(qs1, sKt[1][k], fmaf(qs2, sKt[2][k], qs3 * sKt[3][k])));
        m = fmaxf(m, s);
    }

    // pass 2: denom + weighted V
    const unsigned long long nm = pk2(-m, -m);
    float denom = 0.f;
    unsigned long long acc0 = 0, acc1 = 0, acc2 = 0, acc3 = 0;
    for (int i = 0; i < nquad; i++) {
        const int k4 = i << 2;
        ulonglong2 k0 = *(const ulonglong2*)&sKt[0][k4];
        ulonglong2 k1 = *(const ulonglong2*)&sKt[1][k4];
        ulonglong2 k2 = *(const ulonglong2*)&sKt[2][k4];
        ulonglong2 k3 = *(const ulonglong2*)&sKt[3][k4];
        unsigned long long s01 = nm, s23 = nm;
        fma2(s01, aq0, k0.x); fma2(s23, aq0, k0.y);
        fma2(s01, aq1, k1.x); fma2(s23, aq1, k1.y);
        fma2(s01, aq2, k2.x); fma2(s23, aq2, k2.y);
        fma2(s01, aq3, k3.x); fma2(s23, aq3, k3.y);
        float2 f01 = up2(s01), f23 = up2(s23);
        float p0 = ex2(f01.x), p1 = ex2(f01.y), p2 = ex2(f23.x), p3 = ex2(f23.y);
        denom += (p0 + p1) + (p2 + p3);
        const float* vb = &sV[k4 * 8];
        {
            unsigned long long P = pk2(p0, p0);
            ulonglong2 va = *(const ulonglong2*)(vb);
            ulonglong2 vc = *(const ulonglong2*)(vb + 4);
            fma2(acc0, P, va.x); fma2(acc1, P, va.y); fma2(acc2, P, vc.x); fma2(acc3, P, vc.y);
        }
        {
            unsigned long long P = pk2(p1, p1);
            ulonglong2 va = *(const ulonglong2*)(vb + 8);
            ulonglong2 vc = *(const ulonglong2*)(vb + 12);
            fma2(acc0, P, va.x); fma2(acc1, P, va.y); fma2(acc2, P, vc.x); fma2(acc3, P, vc.y);
        }
        {
            unsigned long long P = pk2(p2, p2);
            ulonglong2 va = *(const ulonglong2*)(vb + 16);
            ulonglong2 vc = *(const ulonglong2*)(vb + 20);
            fma2(acc0, P, va.x); fma2(acc1, P, va.y); fma2(acc2, P, vc.x); fma2(acc3, P, vc.y);
        }
        {
            unsigned long long P = pk2(p3, p3);
            ulonglong2 va = *(const ulonglong2*)(vb + 24);
            ulonglong2 vc = *(const ulonglong2*)(vb + 28);
            fma2(acc0, P, va.x); fma2(acc1, P, va.y); fma2(acc2, P, vc.x); fma2(acc3, P, vc.y);
        }
    }
    for (int k = nquad << 2; k < n; k++) {
        float s = -m + fmaf(qs0, sKt[0][k], fmaf(qs1, sKt[1][k], fmaf(qs2, sKt[2][k], qs3 * sKt[3][k])));
        float p = ex2(s);
        denom += p;
        unsigned long long P = pk2(p, p);
        const float* vb = &sV[k * 8];
        ulonglong2 va = *(const ulonglong2*)(vb);
        ulonglong2 vc = *(const ulonglong2*)(vb + 4);
        fma2(acc0, P, va.x); fma2(acc1, P, va.y); fma2(acc2, P, vc.x); fma2(acc3, P, vc.y);
    }

    if (CAUSAL) {
        float pm = ex2(-m);                       // weight of each masked key
        denom += (float)(SEQ - 1 - q) * pm;
        unsigned long long P = pk2(pm, pm);
        unsigned long long sp0 = pk2(suf[0], suf[1]);
        unsigned long long sp1 = pk2(suf[2], suf[3]);
        unsigned long long sp2 = pk2(suf[4], suf[5]);
        unsigned long long sp3 = pk2(suf[6], suf[7]);
        fma2(acc0, P, sp0); fma2(acc1, P, sp1); fma2(acc2, P, sp2); fma2(acc3, P, sp3);
    }

    const float inv = 1.0f / denom;
    float2 o0 = up2(acc0), o1 = up2(acc1), o2 = up2(acc2), o3 = up2(acc3);
    float* o = Out + rowbase * DM + h * 8;
    *(float4*)(o)     = make_float4(o0.x * inv, o0.y * inv, o1.x * inv, o1.y * inv);
    *(float4*)(o + 4) = make_float4(o2.x * inv, o2.y * inv, o3.x * inv, o3.y * inv);
}

// ---------------- Residual + LayerNorm + FFN (hidden=10) fused ----------------
#define HIDD 10
__global__ __launch_bounds__(256) void lnffn_k(
    const float* __restrict__ x, const float* __restrict__ fx,
    const float* __restrict__ lg, const float* __restrict__ lb,
    const float* __restrict__ w1, const float* __restrict__ b1,
    const float* __restrict__ w2, const float* __restrict__ b2,
    float* __restrict__ out)
{
    const int row = blockIdx.x;
    const int t = threadIdx.x;
    const int warp = t >> 5, lane = t & 31;

    const float* xr = x + row * DM;
    const float* fr = fx + row * DM;
    float v0 = xr[t] + fr[t];
    float v1 = xr[t + 256] + fr[t + 256];

    float s = v0 + v1;
    float ss = v0 * v0 + v1 * v1;
#pragma unroll
    for (int o = 16; o > 0; o >>= 1) {
        s  += __shfl_down_sync(0xffffffffu, s,  o);
        ss += __shfl_down_sync(0xffffffffu, ss, o);
    }
    __shared__ float rs[8], rss[8];
    if (lane == 0) { rs[warp] = s; rss[warp] = ss; }
    __syncthreads();
    float S = 0.f, SS = 0.f;
#pragma unroll
    for (int w = 0; w < 8; w++) { S += rs[w]; SS += rss[w]; }
    const float mu = S * (1.0f / DM);
    const float var = SS * (1.0f / DM) - mu * mu;
    const float rstd = rsqrtf(var + 1e-5f);

    const float y0 = (v0 - mu) * rstd * lg[t] + lb[t];
    const float y1 = (v1 - mu) * rstd * lg[t + 256] + lb[t + 256];

    float pj[HIDD];
#pragma unroll
    for (int j = 0; j < HIDD; j++)
        pj[j] = y0 * __ldg(&w1[j * DM + t]) + y1 * __ldg(&w1[j * DM + t + 256]);
#pragma unroll
    for (int j = 0; j < HIDD; j++)
#pragma unroll
        for (int o = 16; o > 0; o >>= 1)
            pj[j] += __shfl_down_sync(0xffffffffu, pj[j], o);

    __shared__ float hred[8][HIDD];
    if (lane == 0)
#pragma unroll
        for (int j = 0; j < HIDD; j++) hred[warp][j] = pj[j];
    __syncthreads();

    __shared__ float sh[HIDD];
    if (t < HIDD) {
        float hv = b1[t];
#pragma unroll
        for (int w = 0; w < 8; w++) hv += hred[w][t];
        sh[t] = fmaxf(hv, 0.f);
    }
    __syncthreads();

    float o0 = b2[t], o1 = b2[t + 256];
#pragma unroll
    for (int j = 0; j < HIDD; j++) {
        const float hj = sh[j];
        o0 = fmaf(hj, __ldg(&w2[t * HIDD + j]), o0);
        o1 = fmaf(hj, __ldg(&w2[(t + 256) * HIDD + j]), o1);
    }
    out[row * DM + t] = o0;
    out[row * DM + t + 256] = o1;
}

// ---------------- launch ----------------
extern "C" void kernel_launch(void* const* d_in, const int* in_sizes, int n_in,
                              void* d_out, int out_size)
{
    const float* x   = (const float*)d_in[0];
    const float* xe  = (const float*)d_in[1];
    const float* Wq  = (const float*)d_in[2];
    const float* Wk  = (const float*)d_in[3];
    const float* Wv  = (const float*)d_in[4];
    const float* lg  = (const float*)d_in[5];
    const float* lb  = (const float*)d_in[6];
    const float* w1  = (const float*)d_in[7];
    const float* b1  = (const float*)d_in[8];
    const float* w2  = (const float*)d_in[9];
    const float* b2  = (const float*)d_in[10];
    float* out = (float*)d_out;

    float *qkv, *kvenc, *q2a, *q2b, *fx, *fx2, *W;
    cudaGetSymbolAddress((void**)&qkv,   g_qkv);
    cudaGetSymbolAddress((void**)&kvenc, g_kvenc);
    cudaGetSymbolAddress((void**)&q2a,   g_q2a);
    cudaGetSymbolAddress((void**)&q2b,   g_q2b);
    cudaGetSymbolAddress((void**)&fx,    g_fx);
    cudaGetSymbolAddress((void**)&fx2,   g_fx2);
    cudaGetSymbolAddress((void**)&W,     g_W);

    // pack weights [Wq|Wk|Wv]
    packW_k<<<512, 256>>>((const float4*)Wq, (const float4*)Wk, (const float4*)Wv, (float4*)W);

    // fused projections: self QKV + encoder KV, 896 blocks, double-buffered
    proj_k<<<896, 256>>>(x, xe, W, qkv, kvenc);

    // self-attention (multiplicative causal mask quirk + suffix-sum fast path)
    attn2_k<1, 0><<<512, 512>>>(qkv, nullptr, 1024, 0, qkv, 1024, 256, 512, fx);

    // cross-attention Q projection (split-K=2, partials summed in attn)
    crossq_k<<<dim3(4, 64, 2), 256>>>(fx, Wq, q2a, q2b);

    // cross-attention (no mask), Q = q2a + q2b
    attn2_k<0, 1><<<512, 512>>>(q2a, q2b, 256, 0, kvenc, 768, 0, 256, fx2);

    // residual + LN + FFN
    lnffn_k<<<4096, 256>>>(x, fx2, lg, lb, w1, b1, w2, b2, out);
}

// round 5
// speedup vs baseline: 1.6534x; 1.0283x over previous
#include <cuda_runtime.h>
#include <cuda_bf16.h>
#include <cstdint>

#define BS 8
#define SEQ 512
#define DM 512
#define NROW (BS*SEQ)          // 4096
#define KEXT 3072              // 6 segments x 512
#define NCH 96                 // KEXT / 32

// ---------------- scratch (no allocation allowed) ----------------
__device__ __align__(16) float g_qkv[NROW * 1024];    // [Q(256)|K(256)|V(512)] self
__device__ __align__(16) float g_kvenc[NROW * 768];   // [K(256)|V(512)] encoder
__device__ __align__(16) float g_q2[NROW * 256];      // cross-attention Q
__device__ __align__(16) float g_fx[NROW * 512];      // self-attn output
__device__ __align__(16) float g_fx2[NROW * 512];     // cross-attn output
__device__ __align__(16) __nv_bfloat16 g_xs [NROW * KEXT];   // x   split-extended
__device__ __align__(16) __nv_bfloat16 g_xes[NROW * KEXT];   // xe  split-extended
__device__ __align__(16) __nv_bfloat16 g_fxs[NROW * KEXT];   // fx  split-extended
__device__ __align__(16) __nv_bfloat16 g_ball[1792 * KEXT];  // [Wq|Wk|Wv|Wk|Wv]^T split

// ---------------- helpers ----------------
__device__ __forceinline__ uint32_t smem_u32(const void* p) {
    uint32_t a;
    asm("{ .reg .u64 t; cvta.to.shared.u64 t, %1; cvt.u32.u64 %0, t; }" : "=r"(a) : "l"(p));
    return a;
}
__device__ __forceinline__ float ex2(float x) {
    float y; asm("ex2.approx.f32 %0, %1;" : "=f"(y) : "f"(x)); return y;
}
__device__ __forceinline__ unsigned long long pk2(float x, float y) {
    unsigned long long r; asm("mov.b64 %0, {%1,%2};" : "=l"(r) : "f"(x), "f"(y)); return r;
}
__device__ __forceinline__ void fma2(unsigned long long& d, unsigned long long a, unsigned long long b) {
    asm("fma.rn.f32x2 %0, %1, %2, %0;" : "+l"(d) : "l"(a), "l"(b));
}
__device__ __forceinline__ float2 up2(unsigned long long v) {
    float2 r; asm("mov.b64 {%0,%1}, %2;" : "=f"(r.x), "=f"(r.y) : "l"(v)); return r;
}
__device__ __forceinline__ void cpasync16(uint32_t dst, const void* src) {
    asm volatile("cp.async.cg.shared.global [%0], [%1], 16;" :: "r"(dst), "l"(src));
}

// ---------------- split kernels (fp32 -> 6-segment bf16 K-extension) ----------------
__device__ __forceinline__ void split3(float v, __nv_bfloat16& h, __nv_bfloat16& m, __nv_bfloat16& l) {
    h = __float2bfloat16(v);
    float r1 = v - __bfloat162float(h);
    m = __float2bfloat16(r1);
    float r2 = r1 - __bfloat162float(m);
    l = __float2bfloat16(r2);
}

// A segments: [hi, hi, mid, hi, lo, mid]
__global__ __launch_bounds__(256) void splitA_k(const float* __restrict__ in, __nv_bfloat16* __restrict__ out)
{
    int id = blockIdx.x * 256 + threadIdx.x;   // NROW*512 elements
    int r = id >> 9, c = id & 511;
    __nv_bfloat16 h, m, l;
    split3(in[id], h, m, l);
    __nv_bfloat16* o = out + (size_t)r * KEXT + c;
    o[0] = h; o[512] = h; o[1024] = m; o[1536] = h; o[2048] = l; o[2560] = m;
}

// B rows: g_ball[n][k] = W[k][n] split into segments [hi, mid, hi, lo, hi, mid]
__global__ void splitW_k(const float* __restrict__ Wq, const float* __restrict__ Wk,
                         const float* __restrict__ Wv, __nv_bfloat16* __restrict__ out)
{
    __shared__ float s[32][33];
    const int k0 = blockIdx.x * 32, n0 = blockIdx.y * 32;
    const int tx = threadIdx.x, ty = threadIdx.y;   // 32 x 8

    const float* src; int col0, ldw;
    if      (n0 < 256)  { src = Wq; col0 = n0;        ldw = 256; }
    else if (n0 < 512)  { src = Wk; col0 = n0 - 256;  ldw = 256; }
    else if (n0 < 1024) { src = Wv; col0 = n0 - 512;  ldw = 512; }
    else if (n0 < 1280) { src = Wk; col0 = n0 - 1024; ldw = 256; }
    else                { src = Wv; col0 = n0 - 1280; ldw = 512; }

#pragma unroll
    for (int i = 0; i < 4; i++) {
        int kk = ty + i * 8;
        s[kk][tx] = src[(k0 + kk) * ldw + col0 + tx];
    }
    __syncthreads();
#pragma unroll
    for (int i = 0; i < 4; i++) {
        int nn = ty + i * 8;
        __nv_bfloat16 h, m, l;
        split3(s[tx][nn], h, m, l);
        __nv_bfloat16* o = out + (size_t)(n0 + nn) * KEXT + k0 + tx;
        o[0] = h; o[512] = m; o[1024] = h; o[1536] = l; o[2048] = h; o[2560] = m;
    }
}

// ---------------- mma.sync bf16 GEMM: 128x128 CTA tile, K_ext = 3072 ----------------
// 8 warps as 2(m) x 4(n); warp tile 64x32; m16n8k16 atoms; KC=32 chunks, cp.async x2 stages.
__global__ __launch_bounds__(256, 2) void mmagemm_k(
    const __nv_bfloat16* __restrict__ A0, const __nv_bfloat16* __restrict__ B0,
    float* __restrict__ C0, int ldc0, int nt0, int nblk0,
    const __nv_bfloat16* __restrict__ A1, const __nv_bfloat16* __restrict__ B1,
    float* __restrict__ C1, int ldc1, int nt1)
{
    __shared__ __align__(16) __nv_bfloat16 sA[2][128][40];   // 40 = 32 + pad (bank-perfect)
    __shared__ __align__(16) __nv_bfloat16 sB[2][128][40];

    const int tid = threadIdx.x;
    const int wid = tid >> 5, lane = tid & 31;

    const __nv_bfloat16 *A, *B; float* C; int ldc, bx, by;
    {
        int bid = blockIdx.x;
        if (bid < nblk0) { bx = bid % nt0; by = bid / nt0; A = A0; B = B0; C = C0; ldc = ldc0; }
        else { bid -= nblk0; bx = bid % nt1; by = bid / nt1; A = A1; B = B1; C = C1; ldc = ldc1; }
    }
    A += (size_t)by * 128 * KEXT;
    B += (size_t)bx * 128 * KEXT;
    C += (size_t)by * 128 * ldc + bx * 128;

    const uint32_t sAb = smem_u32(&sA[0][0][0]);
    const uint32_t sBb = smem_u32(&sB[0][0][0]);
    const uint32_t STAGE = 128 * 80;   // bytes per stage

    // issue cp.async loads of chunk c into buffer buf (4 x 16B per thread)
    auto issue = [&](int c, int buf) {
#pragma unroll
        for (int i = 0; i < 2; i++) {
            int g = tid + i * 256;           // 0..511
            int r = g >> 2, j = g & 3;
            uint32_t so = (uint32_t)buf * STAGE + r * 80 + j * 16;
            const char* ga = (const char*)(A + (size_t)r * KEXT + c * 32 + j * 8);
            cpasync16(sAb + so, ga);
            const char* gb = (const char*)(B + (size_t)r * KEXT + c * 32 + j * 8);
            cpasync16(sBb + so, gb);
        }
    };

    issue(0, 0);
    asm volatile("cp.async.commit_group;" ::: "memory");
    issue(1, 1);
    asm volatile("cp.async.commit_group;" ::: "memory");

    float acc[4][4][4];
#pragma unroll
    for (int i = 0; i < 4; i++)
#pragma unroll
        for (int j = 0; j < 4; j++)
#pragma unroll
            for (int k = 0; k < 4; k++) acc[i][j][k] = 0.f;

    const int wm = wid >> 2, wn = wid & 3;
    const int rbase = wm * 64 + (lane >> 2);
    const int nbase = wn * 32 + (lane >> 2);
    const int lq = lane & 3;

    for (int c = 0; c < NCH; c++) {
        asm volatile("cp.async.wait_group 1;" ::: "memory");
        __syncthreads();
        const uint32_t* sA32 = (const uint32_t*)&sA[c & 1][0][0];
        const uint32_t* sB32 = (const uint32_t*)&sB[c & 1][0][0];

#pragma unroll
        for (int ks = 0; ks < 2; ks++) {
            const int cw = ks * 8 + lq;
            uint32_t af[4][4], bf[4][2];
#pragma unroll
            for (int am = 0; am < 4; am++) {
                int r = rbase + am * 16;
                af[am][0] = sA32[r * 20 + cw];
                af[am][1] = sA32[(r + 8) * 20 + cw];
                af[am][2] = sA32[r * 20 + cw + 4];
                af[am][3] = sA32[(r + 8) * 20 + cw + 4];
            }
#pragma unroll
            for (int an = 0; an < 4; an++) {
                int n = nbase + an * 8;
                bf[an][0] = sB32[n * 20 + cw];
                bf[an][1] = sB32[n * 20 + cw + 4];
            }
#pragma unroll
            for (int am = 0; am < 4; am++)
#pragma unroll
                for (int an = 0; an < 4; an++) {
                    asm volatile(
                        "mma.sync.aligned.m16n8k16.row.col.f32.bf16.bf16.f32 "
                        "{%0,%1,%2,%3}, {%4,%5,%6,%7}, {%8,%9}, {%0,%1,%2,%3};"
                        : "+f"(acc[am][an][0]), "+f"(acc[am][an][1]),
                          "+f"(acc[am][an][2]), "+f"(acc[am][an][3])
                        : "r"(af[am][0]), "r"(af[am][1]), "r"(af[am][2]), "r"(af[am][3]),
                          "r"(bf[an][0]), "r"(bf[an][1]));
                }
        }
        __syncthreads();
        if (c + 2 < NCH) issue(c + 2, c & 1);
        asm volatile("cp.async.commit_group;" ::: "memory");
    }

    // epilogue
#pragma unroll
    for (int am = 0; am < 4; am++) {
#pragma unroll
        for (int an = 0; an < 4; an++) {
            int r0 = wm * 64 + am * 16 + (lane >> 2);
            int cc = wn * 32 + an * 8 + lq * 2;
            *(float2*)&C[r0 * ldc + cc]       = make_float2(acc[am][an][0], acc[am][an][1]);
            *(float2*)&C[(r0 + 8) * ldc + cc] = make_float2(acc[am][an][2], acc[am][an][3]);
        }
    }
}

// ---------------- Attention (FFMA2, base-2 softmax, causal suffix trick) ----------------
template <int CAUSAL>
__global__ __launch_bounds__(512, 2) void attn2_k(
    const float* __restrict__ Qbuf, int ldq, int qoff,
    const float* __restrict__ KVbuf, int ldkv, int koff, int voff,
    float* __restrict__ Out)
{
    __shared__ float sKt[4][512];                 // K transposed: [dim][key]
    __shared__ __align__(16) float sV[512 * 8];   // V row-major:  [key][dim]
    __shared__ float sWS[16][8];                  // warp V-sums for suffix scan

    const int bh = blockIdx.x;
    const int h = bh & 63, b = bh >> 6;
    const int t = threadIdx.x, lane = t & 31, wid = t >> 5;
    const int rowbase = b * SEQ + t;

    const float* kv = KVbuf + rowbase * ldkv;
    float4 kk = *(const float4*)(kv + koff + h * 4);
    sKt[0][t] = kk.x; sKt[1][t] = kk.y; sKt[2][t] = kk.z; sKt[3][t] = kk.w;
    float4 v0 = *(const float4*)(kv + voff + h * 8);
    float4 v1 = *(const float4*)(kv + voff + h * 8 + 4);
    *(float4*)&sV[t * 8] = v0;
    *(float4*)&sV[t * 8 + 4] = v1;

    float suf[8];
    if (CAUSAL) {
        float vown[8] = {v0.x, v0.y, v0.z, v0.w, v1.x, v1.y, v1.z, v1.w};
#pragma unroll
        for (int d = 0; d < 8; d++) suf[d] = vown[d];
#pragma unroll
        for (int off = 1; off < 32; off <<= 1) {
#pragma unroll
            for (int d = 0; d < 8; d++) {
                float o = __shfl_down_sync(0xffffffffu, suf[d], off);
                if (lane + off < 32) suf[d] += o;
            }
        }
        if (lane == 0) {
#pragma unroll
            for (int d = 0; d < 8; d++) sWS[wid][d] = suf[d];
        }
        __syncthreads();
        for (int w = wid + 1; w < 16; w++)
#pragma unroll
            for (int d = 0; d < 8; d++) suf[d] += sWS[w][d];
#pragma unroll
        for (int d = 0; d < 8; d++) suf[d] -= vown[d];   // sum_{k > t}
    } else {
        __syncthreads();
    }

    const int q = t;
    const float SCQ = 0.72134752044448170f;  // 0.5 * log2(e)
    float4 qv = *(const float4*)(Qbuf + rowbase * ldq + qoff + h * 4);
    const float qs0 = qv.x * SCQ, qs1 = qv.y * SCQ, qs2 = qv.z * SCQ, qs3 = qv.w * SCQ;
    unsigned long long aq0 = pk2(qs0, qs0), aq1 = pk2(qs1, qs1);
    unsigned long long aq2 = pk2(qs2, qs2), aq3 = pk2(qs3, qs3);

    const int n = CAUSAL ? (q + 1) : SEQ;
    const int nquad = n >> 2;

    float m = CAUSAL ? 0.f : -3.0e38f;
    for (int i = 0; i < nquad; i++) {
        const int k4 = i << 2;
        ulonglong2 k0 = *(const ulonglong2*)&sKt[0][k4];
        ulonglong2 k1 = *(const ulonglong2*)&sKt[1][k4];
        ulonglong2 k2 = *(const ulonglong2*)&sKt[2][k4];
        ulonglong2 k3 = *(const ulonglong2*)&sKt[3][k4];
        unsigned long long s01 = 0ULL, s23 = 0ULL;
        fma2(s01, aq0, k0.x); fma2(s23, aq0, k0.y);
        fma2(s01, aq1, k1.x); fma2(s23, aq1, k1.y);
        fma2(s01, aq2, k2.x); fma2(s23, aq2, k2.y);
        fma2(s01, aq3, k3.x); fma2(s23, aq3, k3.y);
        float2 f01 = up2(s01), f23 = up2(s23);
        m = fmaxf(m, fmaxf(fmaxf(f01.x, f01.y), fmaxf(f23.x, f23.y)));
    }
    for (int k = nquad << 2; k < n; k++) {
        float s = fmaf(qs0, sKt[0][k], fmaf(qs1, sKt[1][k], fmaf(qs2, sKt[2][k], qs3 * sKt[3][k])));
        m = fmaxf(m, s);
    }

    const unsigned long long nm = pk2(-m, -m);
    float denom = 0.f;
    unsigned long long acc0 = 0, acc1 = 0, acc2 = 0, acc3 = 0;
    for (int i = 0; i < nquad; i++) {
        const int k4 = i << 2;
        ulonglong2 k0 = *(const ulonglong2*)&sKt[0][k4];
        ulonglong2 k1 = *(const ulonglong2*)&sKt[1][k4];
        ulonglong2 k2 = *(const ulonglong2*)&sKt[2][k4];
        ulonglong2 k3 = *(const ulonglong2*)&sKt[3][k4];
        unsigned long long s01 = nm, s23 = nm;
        fma2(s01, aq0, k0.x); fma2(s23, aq0, k0.y);
        fma2(s01, aq1, k1.x); fma2(s23, aq1, k1.y);
        fma2(s01, aq2, k2.x); fma2(s23, aq2, k2.y);
        fma2(s01, aq3, k3.x); fma2(s23, aq3, k3.y);
        float2 f01 = up2(s01), f23 = up2(s23);
        float p0 = ex2(f01.x), p1 = ex2(f01.y), p2 = ex2(f23.x), p3 = ex2(f23.y);
        denom += (p0 + p1) + (p2 + p3);
        const float* vb = &sV[k4 * 8];
        {
            unsigned long long P = pk2(p0, p0);
            ulonglong2 va = *(const ulonglong2*)(vb);
            ulonglong2 vc = *(const ulonglong2*)(vb + 4);
            fma2(acc0, P, va.x); fma2(acc1, P, va.y); fma2(acc2, P, vc.x); fma2(acc3, P, vc.y);
        }
        {
            unsigned long long P = pk2(p1, p1);
            ulonglong2 va = *(const ulonglong2*)(vb + 8);
            ulonglong2 vc = *(const ulonglong2*)(vb + 12);
            fma2(acc0, P, va.x); fma2(acc1, P, va.y); fma2(acc2, P, vc.x); fma2(acc3, P, vc.y);
        }
        {
            unsigned long long P = pk2(p2, p2);
            ulonglong2 va = *(const ulonglong2*)(vb + 16);
            ulonglong2 vc = *(const ulonglong2*)(vb + 20);
            fma2(acc0, P, va.x); fma2(acc1, P, va.y); fma2(acc2, P, vc.x); fma2(acc3, P, vc.y);
        }
        {
            unsigned long long P = pk2(p3, p3);
            ulonglong2 va = *(const ulonglong2*)(vb + 24);
            ulonglong2 vc = *(const ulonglong2*)(vb + 28);
            fma2(acc0, P, va.x); fma2(acc1, P, va.y); fma2(acc2, P, vc.x); fma2(acc3, P, vc.y);
        }
    }
    for (int k = nquad << 2; k < n; k++) {
        float s = -m + fmaf(qs0, sKt[0][k], fmaf(qs1, sKt[1][k], fmaf(qs2, sKt[2][k], qs3 * sKt[3][k])));
        float p = ex2(s);
        denom += p;
        unsigned long long P = pk2(p, p);
        const float* vb = &sV[k * 8];
        ulonglong2 va = *(const ulonglong2*)(vb);
        ulonglong2 vc = *(const ulonglong2*)(vb + 4);
        fma2(acc0, P, va.x); fma2(acc1, P, va.y); fma2(acc2, P, vc.x); fma2(acc3, P, vc.y);
    }

    if (CAUSAL) {
        float pm = ex2(-m);
        denom += (float)(SEQ - 1 - q) * pm;
        unsigned long long P = pk2(pm, pm);
        fma2(acc0, P, pk2(suf[0], suf[1]));
        fma2(acc1, P, pk2(suf[2], suf[3]));
        fma2(acc2, P, pk2(suf[4], suf[5]));
        fma2(acc3, P, pk2(suf[6], suf[7]));
    }

    const float inv = 1.0f / denom;
    float2 o0 = up2(acc0), o1 = up2(acc1), o2 = up2(acc2), o3 = up2(acc3);
    float* o = Out + rowbase * DM + h * 8;
    *(float4*)(o)     = make_float4(o0.x * inv, o0.y * inv, o1.x * inv, o1.y * inv);
    *(float4*)(o + 4) = make_float4(o2.x * inv, o2.y * inv, o3.x * inv, o3.y * inv);
}

// ---------------- Residual + LayerNorm + FFN (hidden=10) fused ----------------
#define HIDD 10
__global__ __launch_bounds__(256) void lnffn_k(
    const float* __restrict__ x, const float* __restrict__ fx,
    const float* __restrict__ lg, const float* __restrict__ lb,
    const float* __restrict__ w1, const float* __restrict__ b1,
    const float* __restrict__ w2, const float* __restrict__ b2,
    float* __restrict__ out)
{
    const int row = blockIdx.x;
    const int t = threadIdx.x;
    const int warp = t >> 5, lane = t & 31;

    const float* xr = x + row * DM;
    const float* fr = fx + row * DM;
    float v0 = xr[t] + fr[t];
    float v1 = xr[t + 256] + fr[t + 256];

    float s = v0 + v1;
    float ss = v0 * v0 + v1 * v1;
#pragma unroll
    for (int o = 16; o > 0; o >>= 1) {
        s  += __shfl_down_sync(0xffffffffu, s,  o);
        ss += __shfl_down_sync(0xffffffffu, ss, o);
    }
    __shared__ float rs[8], rss[8];
    if (lane == 0) { rs[warp] = s; rss[warp] = ss; }
    __syncthreads();
    float S = 0.f, SS = 0.f;
#pragma unroll
    for (int w = 0; w < 8; w++) { S += rs[w]; SS += rss[w]; }
    const float mu = S * (1.0f / DM);
    const float var = SS * (1.0f / DM) - mu * mu;
    const float rstd = rsqrtf(var + 1e-5f);

    const float y0 = (v0 - mu) * rstd * lg[t] + lb[t];
    const float y1 = (v1 - mu) * rstd * lg[t + 256] + lb[t + 256];

    float pj[HIDD];
#pragma unroll
    for (int j = 0; j < HIDD; j++)
        pj[j] = y0 * __ldg(&w1[j * DM + t]) + y1 * __ldg(&w1[j * DM + t + 256]);
#pragma unroll
    for (int j = 0; j < HIDD; j++)
#pragma unroll
        for (int o = 16; o > 0; o >>= 1)
            pj[j] += __shfl_down_sync(0xffffffffu, pj[j], o);

    __shared__ float hred[8][HIDD];
    if (lane == 0)
#pragma unroll
        for (int j = 0; j < HIDD; j++) hred[warp][j] = pj[j];
    __syncthreads();

    __shared__ float sh[HIDD];
    if (t < HIDD) {
        float hv = b1[t];
#pragma unroll
        for (int w = 0; w < 8; w++) hv += hred[w][t];
        sh[t] = fmaxf(hv, 0.f);
    }
    __syncthreads();

    float o0 = b2[t], o1 = b2[t + 256];
#pragma unroll
    for (int j = 0; j < HIDD; j++) {
        const float hj = sh[j];
        o0 = fmaf(hj, __ldg(&w2[t * HIDD + j]), o0);
        o1 = fmaf(hj, __ldg(&w2[(t + 256) * HIDD + j]), o1);
    }
    out[row * DM + t] = o0;
    out[row * DM + t + 256] = o1;
}

// ---------------- launch ----------------
extern "C" void kernel_launch(void* const* d_in, const int* in_sizes, int n_in,
                              void* d_out, int out_size)
{
    const float* x   = (const float*)d_in[0];
    const float* xe  = (const float*)d_in[1];
    const float* Wq  = (const float*)d_in[2];
    const float* Wk  = (const float*)d_in[3];
    const float* Wv  = (const float*)d_in[4];
    const float* lg  = (const float*)d_in[5];
    const float* lb  = (const float*)d_in[6];
    const float* w1  = (const float*)d_in[7];
    const float* b1  = (const float*)d_in[8];
    const float* w2  = (const float*)d_in[9];
    const float* b2  = (const float*)d_in[10];
    float* out = (float*)d_out;

    float *qkv, *kvenc, *q2, *fx, *fx2;
    __nv_bfloat16 *xs, *xes, *fxs, *ball;
    cudaGetSymbolAddress((void**)&qkv,   g_qkv);
    cudaGetSymbolAddress((void**)&kvenc, g_kvenc);
    cudaGetSymbolAddress((void**)&q2,    g_q2);
    cudaGetSymbolAddress((void**)&fx,    g_fx);
    cudaGetSymbolAddress((void**)&fx2,   g_fx2);
    cudaGetSymbolAddress((void**)&xs,    g_xs);
    cudaGetSymbolAddress((void**)&xes,   g_xes);
    cudaGetSymbolAddress((void**)&fxs,   g_fxs);
    cudaGetSymbolAddress((void**)&ball,  g_ball);

    // split inputs + weights into 6-segment bf16 K-extension
    splitA_k<<<8192, 256>>>(x,  xs);
    splitA_k<<<8192, 256>>>(xe, xes);
    splitW_k<<<dim3(16, 56), dim3(32, 8)>>>(Wq, Wk, Wv, ball);

    // fused projections on tensor cores: self QKV (256 tiles) + encoder KV (192 tiles)
    mmagemm_k<<<448, 256>>>(xs, ball, qkv, 1024, 8, 256,
                            xes, ball + (size_t)1024 * KEXT, kvenc, 768, 6);

    // self-attention (multiplicative causal mask quirk + suffix-sum fast path)
    attn2_k<1><<<512, 512>>>(qkv, 1024, 0, qkv, 1024, 256, 512, fx);

    // cross-attention Q projection on tensor cores
    splitA_k<<<8192, 256>>>(fx, fxs);
    mmagemm_k<<<64, 256>>>(fxs, ball, q2, 256, 2, 64,
                           fxs, ball, q2, 256, 2);

    // cross-attention (no mask)
    attn2_k<0><<<512, 512>>>(q2, 256, 0, kvenc, 768, 0, 256, fx2);

    // residual + LN + FFN
    lnffn_k<<<4096, 256>>>(x, fx2, lg, lb, w1, b1, w2, b2, out);
}

// round 6
// speedup vs baseline: 1.7446x; 1.0552x over previous
#include <cuda_runtime.h>
#include <cuda_bf16.h>
#include <cstdint>

#define BS 8
#define SEQ 512
#define DM 512
#define NROW (BS*SEQ)          // 4096
#define KEXT 3072              // 6 segments x 512

// ---------------- scratch (no allocation allowed) ----------------
__device__ __align__(16) float g_qkv[NROW * 1024];    // [Q(256)|K(256)|V(512)] self
__device__ __align__(16) float g_kvenc[NROW * 768];   // [K(256)|V(512)] encoder
__device__ __align__(16) float g_q2a[NROW * 256];     // cross-Q split-K partial 0
__device__ __align__(16) float g_q2b[NROW * 256];     // cross-Q split-K partial 1
__device__ __align__(16) float g_fx2[NROW * 512];     // cross-attn output
__device__ __align__(16) __nv_bfloat16 g_xs [NROW * KEXT];   // x   split-extended
__device__ __align__(16) __nv_bfloat16 g_xes[NROW * KEXT];   // xe  split-extended
__device__ __align__(16) __nv_bfloat16 g_fxs[NROW * KEXT];   // fx  split-extended
__device__ __align__(16) __nv_bfloat16 g_ball[1792 * KEXT];  // [Wq|Wk|Wv|Wk|Wv]^T split

// ---------------- helpers ----------------
__device__ __forceinline__ uint32_t smem_u32(const void* p) {
    uint32_t a;
    asm("{ .reg .u64 t; cvta.to.shared.u64 t, %1; cvt.u32.u64 %0, t; }" : "=r"(a) : "l"(p));
    return a;
}
__device__ __forceinline__ float ex2(float x) {
    float y; asm("ex2.approx.f32 %0, %1;" : "=f"(y) : "f"(x)); return y;
}
__device__ __forceinline__ unsigned long long pk2(float x, float y) {
    unsigned long long r; asm("mov.b64 %0, {%1,%2};" : "=l"(r) : "f"(x), "f"(y)); return r;
}
__device__ __forceinline__ void fma2(unsigned long long& d, unsigned long long a, unsigned long long b) {
    asm("fma.rn.f32x2 %0, %1, %2, %0;" : "+l"(d) : "l"(a), "l"(b));
}
__device__ __forceinline__ float2 up2(unsigned long long v) {
    float2 r; asm("mov.b64 {%0,%1}, %2;" : "=f"(r.x), "=f"(r.y) : "l"(v)); return r;
}
__device__ __forceinline__ void cpasync16(uint32_t dst, const void* src) {
    asm volatile("cp.async.cg.shared.global [%0], [%1], 16;" :: "r"(dst), "l"(src));
}

__device__ __forceinline__ void split3(float v, __nv_bfloat16& h, __nv_bfloat16& m, __nv_bfloat16& l) {
    h = __float2bfloat16(v);
    float r1 = v - __bfloat162float(h);
    m = __float2bfloat16(r1);
    float r2 = r1 - __bfloat162float(m);
    l = __float2bfloat16(r2);
}

// ---------------- split kernels ----------------
// A segments: [hi, hi, mid, hi, lo, mid]; handles x and xe in one launch.
__global__ __launch_bounds__(256) void splitAB_k(const float* __restrict__ x, const float* __restrict__ xe,
                                                 __nv_bfloat16* __restrict__ xs, __nv_bfloat16* __restrict__ xes)
{
    int gid = blockIdx.x * 256 + threadIdx.x;   // 2 * NROW*512
    const float* in; __nv_bfloat16* out; int id;
    if (gid < NROW * 512) { in = x; out = xs; id = gid; }
    else { in = xe; out = xes; id = gid - NROW * 512; }
    int r = id >> 9, c = id & 511;
    __nv_bfloat16 h, m, l;
    split3(in[id], h, m, l);
    __nv_bfloat16* o = out + (size_t)r * KEXT + c;
    o[0] = h; o[512] = h; o[1024] = m; o[1536] = h; o[2048] = l; o[2560] = m;
}

// B rows: g_ball[n][k] = W[k][n], segments [hi, mid, hi, lo, hi, mid]
__global__ void splitW_k(const float* __restrict__ Wq, const float* __restrict__ Wk,
                         const float* __restrict__ Wv, __nv_bfloat16* __restrict__ out)
{
    __shared__ float s[32][33];
    const int k0 = blockIdx.x * 32, n0 = blockIdx.y * 32;
    const int tx = threadIdx.x, ty = threadIdx.y;   // 32 x 8

    const float* src; int col0, ldw;
    if      (n0 < 256)  { src = Wq; col0 = n0;        ldw = 256; }
    else if (n0 < 512)  { src = Wk; col0 = n0 - 256;  ldw = 256; }
    else if (n0 < 1024) { src = Wv; col0 = n0 - 512;  ldw = 512; }
    else if (n0 < 1280) { src = Wk; col0 = n0 - 1024; ldw = 256; }
    else                { src = Wv; col0 = n0 - 1280; ldw = 512; }

#pragma unroll
    for (int i = 0; i < 4; i++) {
        int kk = ty + i * 8;
        s[kk][tx] = src[(k0 + kk) * ldw + col0 + tx];
    }
    __syncthreads();
#pragma unroll
    for (int i = 0; i < 4; i++) {
        int nn = ty + i * 8;
        __nv_bfloat16 h, m, l;
        split3(s[tx][nn], h, m, l);
        __nv_bfloat16* o = out + (size_t)(n0 + nn) * KEXT + k0 + tx;
        o[0] = h; o[512] = m; o[1024] = h; o[1536] = l; o[2048] = h; o[2560] = m;
    }
}

// ---------------- mma.sync GEMM body: 128x128 CTA tile, runtime K ----------------
struct SmemMM {
    __nv_bfloat16 sA[2][128][40];   // 40 = 32 + pad (conflict-free)
    __nv_bfloat16 sB[2][128][40];
};

__device__ __forceinline__ void mma_body(SmemMM& sm,
    const __nv_bfloat16* __restrict__ A, const __nv_bfloat16* __restrict__ B,
    float* __restrict__ C, int ldc, int nch)
{
    const int tid = threadIdx.x;
    const int wid = tid >> 5, lane = tid & 31;

    const uint32_t sAb = smem_u32(&sm.sA[0][0][0]);
    const uint32_t sBb = smem_u32(&sm.sB[0][0][0]);
    const uint32_t STAGE = 128 * 80;

    auto issue = [&](int c, int buf) {
#pragma unroll
        for (int i = 0; i < 2; i++) {
            int g = tid + i * 256;
            int r = g >> 2, j = g & 3;
            uint32_t so = (uint32_t)buf * STAGE + r * 80 + j * 16;
            cpasync16(sAb + so, (const char*)(A + (size_t)r * KEXT + c * 32 + j * 8));
            cpasync16(sBb + so, (const char*)(B + (size_t)r * KEXT + c * 32 + j * 8));
        }
    };

    issue(0, 0);
    asm volatile("cp.async.commit_group;" ::: "memory");
    issue(1, 1);
    asm volatile("cp.async.commit_group;" ::: "memory");

    float acc[4][4][4];
#pragma unroll
    for (int i = 0; i < 4; i++)
#pragma unroll
        for (int j = 0; j < 4; j++)
#pragma unroll
            for (int k = 0; k < 4; k++) acc[i][j][k] = 0.f;

    const int wm = wid >> 2, wn = wid & 3;
    const int rbase = wm * 64 + (lane >> 2);
    const int nbase = wn * 32 + (lane >> 2);
    const int lq = lane & 3;

    for (int c = 0; c < nch; c++) {
        asm volatile("cp.async.wait_group 1;" ::: "memory");
        __syncthreads();
        const uint32_t* sA32 = (const uint32_t*)&sm.sA[c & 1][0][0];
        const uint32_t* sB32 = (const uint32_t*)&sm.sB[c & 1][0][0];

#pragma unroll
        for (int ks = 0; ks < 2; ks++) {
            const int cw = ks * 8 + lq;
            uint32_t af[4][4], bf[4][2];
#pragma unroll
            for (int am = 0; am < 4; am++) {
                int r = rbase + am * 16;
                af[am][0] = sA32[r * 20 + cw];
                af[am][1] = sA32[(r + 8) * 20 + cw];
                af[am][2] = sA32[r * 20 + cw + 4];
                af[am][3] = sA32[(r + 8) * 20 + cw + 4];
            }
#pragma unroll
            for (int an = 0; an < 4; an++) {
                int n = nbase + an * 8;
                bf[an][0] = sB32[n * 20 + cw];
                bf[an][1] = sB32[n * 20 + cw + 4];
            }
#pragma unroll
            for (int am = 0; am < 4; am++)
#pragma unroll
                for (int an = 0; an < 4; an++) {
                    asm volatile(
                        "mma.sync.aligned.m16n8k16.row.col.f32.bf16.bf16.f32 "
                        "{%0,%1,%2,%3}, {%4,%5,%6,%7}, {%8,%9}, {%0,%1,%2,%3};"
                        : "+f"(acc[am][an][0]), "+f"(acc[am][an][1]),
                          "+f"(acc[am][an][2]), "+f"(acc[am][an][3])
                        : "r"(af[am][0]), "r"(af[am][1]), "r"(af[am][2]), "r"(af[am][3]),
                          "r"(bf[an][0]), "r"(bf[an][1]));
                }
        }
        __syncthreads();
        if (c + 2 < nch) issue(c + 2, c & 1);
        asm volatile("cp.async.commit_group;" ::: "memory");
    }

#pragma unroll
    for (int am = 0; am < 4; am++) {
#pragma unroll
        for (int an = 0; an < 4; an++) {
            int r0 = wm * 64 + am * 16 + (lane >> 2);
            int cc = wn * 32 + an * 8 + lq * 2;
            *(float2*)&C[r0 * ldc + cc]       = make_float2(acc[am][an][0], acc[am][an][1]);
            *(float2*)&C[(r0 + 8) * ldc + cc] = make_float2(acc[am][an][2], acc[am][an][3]);
        }
    }
}

// fused projections, 448 blocks, heavy (6-limb) first, light (3-limb enc-V) last:
//   bid <  256 : self QKV   (by=bid>>3, bx=bid&7)   kext 3072
//   bid <  320 : enc K      (i=bid-256: bx=i&1, by=i>>1) kext 3072
//   else       : enc V      (i=bid-320: bx=2+(i&3), by=i>>2) kext 1536 (segs [h,h,m]x[h,m,h])
__global__ __launch_bounds__(256, 2) void proj_k(
    const __nv_bfloat16* __restrict__ xs, const __nv_bfloat16* __restrict__ xes,
    const __nv_bfloat16* __restrict__ ball, float* __restrict__ qkv, float* __restrict__ kvenc)
{
    __shared__ SmemMM sm;
    const int bid = blockIdx.x;
    const __nv_bfloat16 *A, *B; float* C; int ldc, nch, bx, by;
    if (bid < 256) {
        bx = bid & 7; by = bid >> 3;
        A = xs; B = ball; C = qkv; ldc = 1024; nch = 96;
    } else if (bid < 320) {
        int i = bid - 256; bx = i & 1; by = i >> 1;
        A = xes; B = ball + (size_t)1024 * KEXT; C = kvenc; ldc = 768; nch = 96;
    } else {
        int i = bid - 320; bx = 2 + (i & 3); by = i >> 2;
        A = xes; B = ball + (size_t)1024 * KEXT; C = kvenc; ldc = 768; nch = 48;
    }
    mma_body(sm, A + (size_t)by * 128 * KEXT, B + (size_t)bx * 128 * KEXT,
             C + (size_t)by * 128 * ldc + bx * 128, ldc, nch);
}

// cross-Q GEMM: split-K=2 over the 6 segments: half0 = [h,h,m], half1 = [h,l,m]
__global__ __launch_bounds__(256, 2) void crossq_k(
    const __nv_bfloat16* __restrict__ fxs, const __nv_bfloat16* __restrict__ ball,
    float* __restrict__ q2a, float* __restrict__ q2b)
{
    __shared__ SmemMM sm;
    const int bid = blockIdx.x;            // 128
    const int half = bid >> 6;
    const int i = bid & 63;
    const int bx = i & 1, by = i >> 1;
    const __nv_bfloat16* A = fxs + half * 1536;
    const __nv_bfloat16* B = ball + half * 1536;
    float* C = half ? q2b : q2a;
    mma_body(sm, A + (size_t)by * 128 * KEXT, B + (size_t)bx * 128 * KEXT,
             C + (size_t)by * 128 * 256 + bx * 128, 256, 48);
}

// ---------------- Attention (FFMA2, base-2 softmax, causal suffix trick) ----------------
// QSUM: Q = Qbuf + Qbuf2 (split-K). WSPLIT: write split-extended bf16 output to OutS.
template <int CAUSAL, int QSUM, int WSPLIT>
__global__ __launch_bounds__(512, 2) void attn2_k(
    const float* __restrict__ Qbuf, const float* __restrict__ Qbuf2, int ldq, int qoff,
    const float* __restrict__ KVbuf, int ldkv, int koff, int voff,
    float* __restrict__ Out, __nv_bfloat16* __restrict__ OutS)
{
    __shared__ float sKt[4][512];                 // K transposed: [dim][key]
    __shared__ __align__(16) float sV[512 * 8];   // V row-major:  [key][dim]
    __shared__ float sWS[16][8];                  // warp V-sums for suffix scan

    const int bh = blockIdx.x;
    const int h = bh & 63, b = bh >> 6;
    const int t = threadIdx.x, lane = t & 31, wid = t >> 5;
    const int rowbase = b * SEQ + t;

    const float* kv = KVbuf + rowbase * ldkv;
    float4 kk = *(const float4*)(kv + koff + h * 4);
    sKt[0][t] = kk.x; sKt[1][t] = kk.y; sKt[2][t] = kk.z; sKt[3][t] = kk.w;
    float4 v0 = *(const float4*)(kv + voff + h * 8);
    float4 v1 = *(const float4*)(kv + voff + h * 8 + 4);
    *(float4*)&sV[t * 8] = v0;
    *(float4*)&sV[t * 8 + 4] = v1;

    float suf[8];
    if (CAUSAL) {
        float vown[8] = {v0.x, v0.y, v0.z, v0.w, v1.x, v1.y, v1.z, v1.w};
#pragma unroll
        for (int d = 0; d < 8; d++) suf[d] = vown[d];
#pragma unroll
        for (int off = 1; off < 32; off <<= 1) {
#pragma unroll
            for (int d = 0; d < 8; d++) {
                float o = __shfl_down_sync(0xffffffffu, suf[d], off);
                if (lane + off < 32) suf[d] += o;
            }
        }
        if (lane == 0) {
#pragma unroll
            for (int d = 0; d < 8; d++) sWS[wid][d] = suf[d];
        }
        __syncthreads();
        for (int w = wid + 1; w < 16; w++)
#pragma unroll
            for (int d = 0; d < 8; d++) suf[d] += sWS[w][d];
#pragma unroll
        for (int d = 0; d < 8; d++) suf[d] -= vown[d];   // sum_{k > t}
    } else {
        __syncthreads();
    }

    const int q = t;
    const float SCQ = 0.72134752044448170f;  // 0.5 * log2(e)
    float4 qv = *(const float4*)(Qbuf + rowbase * ldq + qoff + h * 4);
    if (QSUM) {
        float4 qv2 = *(const float4*)(Qbuf2 + rowbase * ldq + qoff + h * 4);
        qv.x += qv2.x; qv.y += qv2.y; qv.z += qv2.z; qv.w += qv2.w;
    }
    const float qs0 = qv.x * SCQ, qs1 = qv.y * SCQ, qs2 = qv.z * SCQ, qs3 = qv.w * SCQ;
    unsigned long long aq0 = pk2(qs0, qs0), aq1 = pk2(qs1, qs1);
    unsigned long long aq2 = pk2(qs2, qs2), aq3 = pk2(qs3, qs3);

    const int n = CAUSAL ? (q + 1) : SEQ;
    const int nquad = n >> 2;

    float m = CAUSAL ? 0.f : -3.0e38f;
    for (int i = 0; i < nquad; i++) {
        const int k4 = i << 2;
        ulonglong2 k0 = *(const ulonglong2*)&sKt[0][k4];
        ulonglong2 k1 = *(const ulonglong2*)&sKt[1][k4];
        ulonglong2 k2 = *(const ulonglong2*)&sKt[2][k4];
        ulonglong2 k3 = *(const ulonglong2*)&sKt[3][k4];
        unsigned long long s01 = 0ULL, s23 = 0ULL;
        fma2(s01, aq0, k0.x); fma2(s23, aq0, k0.y);
        fma2(s01, aq1, k1.x); fma2(s23, aq1, k1.y);
        fma2(s01, aq2, k2.x); fma2(s23, aq2, k2.y);
        fma2(s01, aq3, k3.x); fma2(s23, aq3, k3.y);
        float2 f01 = up2(s01), f23 = up2(s23);
        m = fmaxf(m, fmaxf(fmaxf(f01.x, f01.y), fmaxf(f23.x, f23.y)));
    }
    for (int k = nquad << 2; k < n; k++) {
        float s = fmaf(qs0, sKt[0][k], fmaf(qs1, sKt[1][k], fmaf(qs2, sKt[2][k], qs3 * sKt[3][k])));
        m = fmaxf(m, s);
    }

    const unsigned long long nm = pk2(-m, -m);
    float denom = 0.f;
    unsigned long long acc0 = 0, acc1 = 0, acc2 = 0, acc3 = 0;
    for (int i = 0; i < nquad; i++) {
        const int k4 = i << 2;
        ulonglong2 k0 = *(const ulonglong2*)&sKt[0][k4];
        ulonglong2 k1 = *(const ulonglong2*)&sKt[1][k4];
        ulonglong2 k2 = *(const ulonglong2*)&sKt[2][k4];
        ulonglong2 k3 = *(const ulonglong2*)&sKt[3][k4];
        unsigned long long s01 = nm, s23 = nm;
        fma2(s01, aq0, k0.x); fma2(s23, aq0, k0.y);
        fma2(s01, aq1, k1.x); fma2(s23, aq1, k1.y);
        fma2(s01, aq2, k2.x); fma2(s23, aq2, k2.y);
        fma2(s01, aq3, k3.x); fma2(s23, aq3, k3.y);
        float2 f01 = up2(s01), f23 = up2(s23);
        float p0 = ex2(f01.x), p1 = ex2(f01.y), p2 = ex2(f23.x), p3 = ex2(f23.y);
        denom += (p0 + p1) + (p2 + p3);
        const float* vb = &sV[k4 * 8];
        {
            unsigned long long P = pk2(p0, p0);
            ulonglong2 va = *(const ulonglong2*)(vb);
            ulonglong2 vc = *(const ulonglong2*)(vb + 4);
            fma2(acc0, P, va.x); fma2(acc1, P, va.y); fma2(acc2, P, vc.x); fma2(acc3, P, vc.y);
        }
        {
            unsigned long long P = pk2(p1, p1);
            ulonglong2 va = *(const ulonglong2*)(vb + 8);
            ulonglong2 vc = *(const ulonglong2*)(vb + 12);
            fma2(acc0, P, va.x); fma2(acc1, P, va.y); fma2(acc2, P, vc.x); fma2(acc3, P, vc.y);
        }
        {
            unsigned long long P = pk2(p2, p2);
            ulonglong2 va = *(const ulonglong2*)(vb + 16);
            ulonglong2 vc = *(const ulonglong2*)(vb + 20);
            fma2(acc0, P, va.x); fma2(acc1, P, va.y); fma2(acc2, P, vc.x); fma2(acc3, P, vc.y);
        }
        {
            unsigned long long P = pk2(p3, p3);
            ulonglong2 va = *(const ulonglong2*)(vb + 24);
            ulonglong2 vc = *(const ulonglong2*)(vb + 28);
            fma2(acc0, P, va.x); fma2(acc1, P, va.y); fma2(acc2, P, vc.x); fma2(acc3, P, vc.y);
        }
    }
    for (int k = nquad << 2; k < n; k++) {
        float s = -m + fmaf(qs0, sKt[0][k], fmaf(qs1, sKt[1][k], fmaf(qs2, sKt[2][k], qs3 * sKt[3][k])));
        float p = ex2(s);
        denom += p;
        unsigned long long P = pk2(p, p);
        const float* vb = &sV[k * 8];
        ulonglong2 va = *(const ulonglong2*)(vb);
        ulonglong2 vc = *(const ulonglong2*)(vb + 4);
        fma2(acc0, P, va.x); fma2(acc1, P, va.y); fma2(acc2, P, vc.x); fma2(acc3, P, vc.y);
    }

    if (CAUSAL) {
        float pm = ex2(-m);
        denom += (float)(SEQ - 1 - q) * pm;
        unsigned long long P = pk2(pm, pm);
        fma2(acc0, P, pk2(suf[0], suf[1]));
        fma2(acc1, P, pk2(suf[2], suf[3]));
        fma2(acc2, P, pk2(suf[4], suf[5]));
        fma2(acc3, P, pk2(suf[6], suf[7]));
    }

    const float inv = 1.0f / denom;
    float2 o0 = up2(acc0), o1 = up2(acc1), o2 = up2(acc2), o3 = up2(acc3);
    float vals[8] = {o0.x * inv, o0.y * inv, o1.x * inv, o1.y * inv,
                     o2.x * inv, o2.y * inv, o3.x * inv, o3.y * inv};

    if (WSPLIT) {
        // write split-extended bf16 rows (A segments [h,h,m,h,l,m]) directly
        __align__(16) __nv_bfloat16 H[8], M[8], L[8];
#pragma unroll
        for (int d = 0; d < 8; d++) split3(vals[d], H[d], M[d], L[d]);
        __nv_bfloat16* ob = OutS + (size_t)rowbase * KEXT + h * 8;
        *(uint4*)(ob)        = *(uint4*)H;
        *(uint4*)(ob + 512)  = *(uint4*)H;
        *(uint4*)(ob + 1024) = *(uint4*)M;
        *(uint4*)(ob + 1536) = *(uint4*)H;
        *(uint4*)(ob + 2048) = *(uint4*)L;
        *(uint4*)(ob + 2560) = *(uint4*)M;
    } else {
        float* o = Out + rowbase * DM + h * 8;
        *(float4*)(o)     = make_float4(vals[0], vals[1], vals[2], vals[3]);
        *(float4*)(o + 4) = make_float4(vals[4], vals[5], vals[6], vals[7]);
    }
}

// ---------------- Residual + LayerNorm + FFN (hidden=10) fused ----------------
#define HIDD 10
__global__ __launch_bounds__(256) void lnffn_k(
    const float* __restrict__ x, const float* __restrict__ fx,
    const float* __restrict__ lg, const float* __restrict__ lb,
    const float* __restrict__ w1, const float* __restrict__ b1,
    const float* __restrict__ w2, const float* __restrict__ b2,
    float* __restrict__ out)
{
    const int row = blockIdx.x;
    const int t = threadIdx.x;
    const int warp = t >> 5, lane = t & 31;

    const float* xr = x + row * DM;
    const float* fr = fx + row * DM;
    float v0 = xr[t] + fr[t];
    float v1 = xr[t + 256] + fr[t + 256];

    float s = v0 + v1;
    float ss = v0 * v0 + v1 * v1;
#pragma unroll
    for (int o = 16; o > 0; o >>= 1) {
        s  += __shfl_down_sync(0xffffffffu, s,  o);
        ss += __shfl_down_sync(0xffffffffu, ss, o);
    }
    __shared__ float rs[8], rss[8];
    if (lane == 0) { rs[warp] = s; rss[warp] = ss; }
    __syncthreads();
    float S = 0.f, SS = 0.f;
#pragma unroll
    for (int w = 0; w < 8; w++) { S += rs[w]; SS += rss[w]; }
    const float mu = S * (1.0f / DM);
    const float var = SS * (1.0f / DM) - mu * mu;
    const float rstd = rsqrtf(var + 1e-5f);

    const float y0 = (v0 - mu) * rstd * lg[t] + lb[t];
    const float y1 = (v1 - mu) * rstd * lg[t + 256] + lb[t + 256];

    float pj[HIDD];
#pragma unroll
    for (int j = 0; j < HIDD; j++)
        pj[j] = y0 * __ldg(&w1[j * DM + t]) + y1 * __ldg(&w1[j * DM + t + 256]);
#pragma unroll
    for (int j = 0; j < HIDD; j++)
#pragma unroll
        for (int o = 16; o > 0; o >>= 1)
            pj[j] += __shfl_down_sync(0xffffffffu, pj[j], o);

    __shared__ float hred[8][HIDD];
    if (lane == 0)
#pragma unroll
        for (int j = 0; j < HIDD; j++) hred[warp][j] = pj[j];
    __syncthreads();

    __shared__ float sh[HIDD];
    if (t < HIDD) {
        float hv = b1[t];
#pragma unroll
        for (int w = 0; w < 8; w++) hv += hred[w][t];
        sh[t] = fmaxf(hv, 0.f);
    }
    __syncthreads();

    float o0 = b2[t], o1 = b2[t + 256];
#pragma unroll
    for (int j = 0; j < HIDD; j++) {
        const float hj = sh[j];
        o0 = fmaf(hj, __ldg(&w2[t * HIDD + j]), o0);
        o1 = fmaf(hj, __ldg(&w2[(t + 256) * HIDD + j]), o1);
    }
    out[row * DM + t] = o0;
    out[row * DM + t + 256] = o1;
}

// ---------------- launch ----------------
extern "C" void kernel_launch(void* const* d_in, const int* in_sizes, int n_in,
                              void* d_out, int out_size)
{
    const float* x   = (const float*)d_in[0];
    const float* xe  = (const float*)d_in[1];
    const float* Wq  = (const float*)d_in[2];
    const float* Wk  = (const float*)d_in[3];
    const float* Wv  = (const float*)d_in[4];
    const float* lg  = (const float*)d_in[5];
    const float* lb  = (const float*)d_in[6];
    const float* w1  = (const float*)d_in[7];
    const float* b1  = (const float*)d_in[8];
    const float* w2  = (const float*)d_in[9];
    const float* b2  = (const float*)d_in[10];
    float* out = (float*)d_out;

    float *qkv, *kvenc, *q2a, *q2b, *fx2;
    __nv_bfloat16 *xs, *xes, *fxs, *ball;
    cudaGetSymbolAddress((void**)&qkv,   g_qkv);
    cudaGetSymbolAddress((void**)&kvenc, g_kvenc);
    cudaGetSymbolAddress((void**)&q2a,   g_q2a);
    cudaGetSymbolAddress((void**)&q2b,   g_q2b);
    cudaGetSymbolAddress((void**)&fx2,   g_fx2);
    cudaGetSymbolAddress((void**)&xs,    g_xs);
    cudaGetSymbolAddress((void**)&xes,   g_xes);
    cudaGetSymbolAddress((void**)&fxs,   g_fxs);
    cudaGetSymbolAddress((void**)&ball,  g_ball);

    // split inputs + weights into 6-segment bf16 K-extension
    splitAB_k<<<16384, 256>>>(x, xe, xs, xes);
    splitW_k<<<dim3(16, 56), dim3(32, 8)>>>(Wq, Wk, Wv, ball);

    // fused projections (heavy 6-limb tiles first; enc-V 3-limb tiles last)
    proj_k<<<448, 256>>>(xs, xes, ball, qkv, kvenc);

    // self-attention; writes split-extended fxs directly
    attn2_k<1, 0, 1><<<512, 512>>>(qkv, nullptr, 1024, 0, qkv, 1024, 256, 512, nullptr, fxs);

    // cross-attention Q projection (split-K=2 over segment halves)
    crossq_k<<<128, 256>>>(fxs, ball, q2a, q2b);

    // cross-attention (no mask), Q = q2a + q2b
    attn2_k<0, 1, 0><<<512, 512>>>(q2a, q2b, 256, 0, kvenc, 768, 0, 256, fx2, nullptr);

    // residual + LN + FFN
    lnffn_k<<<4096, 256>>>(x, fx2, lg, lb, w1, b1, w2, b2, out);
}

// round 7
// speedup vs baseline: 1.8609x; 1.0666x over previous
#include <cuda_runtime.h>
#include <cuda_bf16.h>
#include <cstdint>

#define BS 8
#define SEQ 512
#define DM 512
#define NROW (BS*SEQ)          // 4096
#define KEXT 3072              // 6 segments x 512

// ---------------- scratch (no allocation allowed) ----------------
__device__ __align__(16) float g_qkv[NROW * 1024];    // [Q(256)|K(256)|V(512)] self
__device__ __align__(16) float g_kvenc[NROW * 768];   // [K(256)|V(512)] encoder
__device__ __align__(16) float g_q2a[NROW * 256];     // cross-Q split-K partial 0
__device__ __align__(16) float g_q2b[NROW * 256];     // cross-Q split-K partial 1
__device__ __align__(16) float g_fx2[NROW * 512];     // cross-attn output
__device__ __align__(16) __nv_bfloat16 g_xs [NROW * KEXT];   // x   split-extended
__device__ __align__(16) __nv_bfloat16 g_xes[NROW * KEXT];   // xe  split-extended
__device__ __align__(16) __nv_bfloat16 g_fxs[NROW * KEXT];   // fx  split-extended
__device__ __align__(16) __nv_bfloat16 g_ball[1792 * KEXT];  // [Wq|Wk|Wv|Wk|Wv]^T split

// ---------------- helpers ----------------
__device__ __forceinline__ uint32_t smem_u32(const void* p) {
    uint32_t a;
    asm("{ .reg .u64 t; cvta.to.shared.u64 t, %1; cvt.u32.u64 %0, t; }" : "=r"(a) : "l"(p));
    return a;
}
__device__ __forceinline__ float ex2(float x) {
    float y; asm("ex2.approx.f32 %0, %1;" : "=f"(y) : "f"(x)); return y;
}
__device__ __forceinline__ unsigned long long pk2(float x, float y) {
    unsigned long long r; asm("mov.b64 %0, {%1,%2};" : "=l"(r) : "f"(x), "f"(y)); return r;
}
__device__ __forceinline__ void fma2(unsigned long long& d, unsigned long long a, unsigned long long b) {
    asm("fma.rn.f32x2 %0, %1, %2, %0;" : "+l"(d) : "l"(a), "l"(b));
}
__device__ __forceinline__ void mul2(unsigned long long& d, unsigned long long a) {
    asm("mul.rn.f32x2 %0, %0, %1;" : "+l"(d) : "l"(a));
}
__device__ __forceinline__ float2 up2(unsigned long long v) {
    float2 r; asm("mov.b64 {%0,%1}, %2;" : "=f"(r.x), "=f"(r.y) : "l"(v)); return r;
}
__device__ __forceinline__ void cpasync16(uint32_t dst, const void* src) {
    asm volatile("cp.async.cg.shared.global [%0], [%1], 16;" :: "r"(dst), "l"(src));
}

__device__ __forceinline__ void split3(float v, __nv_bfloat16& h, __nv_bfloat16& m, __nv_bfloat16& l) {
    h = __float2bfloat16(v);
    float r1 = v - __bfloat162float(h);
    m = __float2bfloat16(r1);
    float r2 = r1 - __bfloat162float(m);
    l = __float2bfloat16(r2);
}

// ---------------- split kernels ----------------
// A segments: [hi, hi, mid, hi, lo, mid]; handles x and xe in one launch.
__global__ __launch_bounds__(256) void splitAB_k(const float* __restrict__ x, const float* __restrict__ xe,
                                                 __nv_bfloat16* __restrict__ xs, __nv_bfloat16* __restrict__ xes)
{
    int gid = blockIdx.x * 256 + threadIdx.x;   // 2 * NROW*512
    const float* in; __nv_bfloat16* out; int id;
    if (gid < NROW * 512) { in = x; out = xs; id = gid; }
    else { in = xe; out = xes; id = gid - NROW * 512; }
    int r = id >> 9, c = id & 511;
    __nv_bfloat16 h, m, l;
    split3(in[id], h, m, l);
    __nv_bfloat16* o = out + (size_t)r * KEXT + c;
    o[0] = h; o[512] = h; o[1024] = m; o[1536] = h; o[2048] = l; o[2560] = m;
}

// B rows: g_ball[n][k] = W[k][n], segments [hi, mid, hi, lo, hi, mid]
__global__ void splitW_k(const float* __restrict__ Wq, const float* __restrict__ Wk,
                         const float* __restrict__ Wv, __nv_bfloat16* __restrict__ out)
{
    __shared__ float s[32][33];
    const int k0 = blockIdx.x * 32, n0 = blockIdx.y * 32;
    const int tx = threadIdx.x, ty = threadIdx.y;   // 32 x 8

    const float* src; int col0, ldw;
    if      (n0 < 256)  { src = Wq; col0 = n0;        ldw = 256; }
    else if (n0 < 512)  { src = Wk; col0 = n0 - 256;  ldw = 256; }
    else if (n0 < 1024) { src = Wv; col0 = n0 - 512;  ldw = 512; }
    else if (n0 < 1280) { src = Wk; col0 = n0 - 1024; ldw = 256; }
    else                { src = Wv; col0 = n0 - 1280; ldw = 512; }

#pragma unroll
    for (int i = 0; i < 4; i++) {
        int kk = ty + i * 8;
        s[kk][tx] = src[(k0 + kk) * ldw + col0 + tx];
    }
    __syncthreads();
#pragma unroll
    for (int i = 0; i < 4; i++) {
        int nn = ty + i * 8;
        __nv_bfloat16 h, m, l;
        split3(s[tx][nn], h, m, l);
        __nv_bfloat16* o = out + (size_t)(n0 + nn) * KEXT + k0 + tx;
        o[0] = h; o[512] = m; o[1024] = h; o[1536] = l; o[2048] = h; o[2560] = m;
    }
}

// ---------------- mma.sync GEMM body: 128x128 CTA tile, runtime K ----------------
struct SmemMM {
    __nv_bfloat16 sA[2][128][40];   // 40 = 32 + pad (conflict-free)
    __nv_bfloat16 sB[2][128][40];
};

__device__ __forceinline__ void mma_body(SmemMM& sm,
    const __nv_bfloat16* __restrict__ A, const __nv_bfloat16* __restrict__ B,
    float* __restrict__ C, int ldc, int nch)
{
    const int tid = threadIdx.x;
    const int wid = tid >> 5, lane = tid & 31;

    const uint32_t sAb = smem_u32(&sm.sA[0][0][0]);
    const uint32_t sBb = smem_u32(&sm.sB[0][0][0]);
    const uint32_t STAGE = 128 * 80;

    auto issue = [&](int c, int buf) {
#pragma unroll
        for (int i = 0; i < 2; i++) {
            int g = tid + i * 256;
            int r = g >> 2, j = g & 3;
            uint32_t so = (uint32_t)buf * STAGE + r * 80 + j * 16;
            cpasync16(sAb + so, (const char*)(A + (size_t)r * KEXT + c * 32 + j * 8));
            cpasync16(sBb + so, (const char*)(B + (size_t)r * KEXT + c * 32 + j * 8));
        }
    };

    issue(0, 0);
    asm volatile("cp.async.commit_group;" ::: "memory");
    issue(1, 1);
    asm volatile("cp.async.commit_group;" ::: "memory");

    float acc[4][4][4];
#pragma unroll
    for (int i = 0; i < 4; i++)
#pragma unroll
        for (int j = 0; j < 4; j++)
#pragma unroll
            for (int k = 0; k < 4; k++) acc[i][j][k] = 0.f;

    const int wm = wid >> 2, wn = wid & 3;
    const int rbase = wm * 64 + (lane >> 2);
    const int nbase = wn * 32 + (lane >> 2);
    const int lq = lane & 3;

    for (int c = 0; c < nch; c++) {
        asm volatile("cp.async.wait_group 1;" ::: "memory");
        __syncthreads();
        const uint32_t* sA32 = (const uint32_t*)&sm.sA[c & 1][0][0];
        const uint32_t* sB32 = (const uint32_t*)&sm.sB[c & 1][0][0];

#pragma unroll
        for (int ks = 0; ks < 2; ks++) {
            const int cw = ks * 8 + lq;
            uint32_t af[4][4], bf[4][2];
#pragma unroll
            for (int am = 0; am < 4; am++) {
                int r = rbase + am * 16;
                af[am][0] = sA32[r * 20 + cw];
                af[am][1] = sA32[(r + 8) * 20 + cw];
                af[am][2] = sA32[r * 20 + cw + 4];
                af[am][3] = sA32[(r + 8) * 20 + cw + 4];
            }
#pragma unroll
            for (int an = 0; an < 4; an++) {
                int n = nbase + an * 8;
                bf[an][0] = sB32[n * 20 + cw];
                bf[an][1] = sB32[n * 20 + cw + 4];
            }
#pragma unroll
            for (int am = 0; am < 4; am++)
#pragma unroll
                for (int an = 0; an < 4; an++) {
                    asm volatile(
                        "mma.sync.aligned.m16n8k16.row.col.f32.bf16.bf16.f32 "
                        "{%0,%1,%2,%3}, {%4,%5,%6,%7}, {%8,%9}, {%0,%1,%2,%3};"
                        : "+f"(acc[am][an][0]), "+f"(acc[am][an][1]),
                          "+f"(acc[am][an][2]), "+f"(acc[am][an][3])
                        : "r"(af[am][0]), "r"(af[am][1]), "r"(af[am][2]), "r"(af[am][3]),
                          "r"(bf[an][0]), "r"(bf[an][1]));
                }
        }
        __syncthreads();
        if (c + 2 < nch) issue(c + 2, c & 1);
        asm volatile("cp.async.commit_group;" ::: "memory");
    }

#pragma unroll
    for (int am = 0; am < 4; am++) {
#pragma unroll
        for (int an = 0; an < 4; an++) {
            int r0 = wm * 64 + am * 16 + (lane >> 2);
            int cc = wn * 32 + an * 8 + lq * 2;
            *(float2*)&C[r0 * ldc + cc]       = make_float2(acc[am][an][0], acc[am][an][1]);
            *(float2*)&C[(r0 + 8) * ldc + cc] = make_float2(acc[am][an][2], acc[am][an][3]);
        }
    }
}

// fused projections, 448 blocks, heavy (6-limb) first, light (3-limb enc-V) last
__global__ __launch_bounds__(256, 2) void proj_k(
    const __nv_bfloat16* __restrict__ xs, const __nv_bfloat16* __restrict__ xes,
    const __nv_bfloat16* __restrict__ ball, float* __restrict__ qkv, float* __restrict__ kvenc)
{
    __shared__ SmemMM sm;
    const int bid = blockIdx.x;
    const __nv_bfloat16 *A, *B; float* C; int ldc, nch, bx, by;
    if (bid < 256) {
        bx = bid & 7; by = bid >> 3;
        A = xs; B = ball; C = qkv; ldc = 1024; nch = 96;
    } else if (bid < 320) {
        int i = bid - 256; bx = i & 1; by = i >> 1;
        A = xes; B = ball + (size_t)1024 * KEXT; C = kvenc; ldc = 768; nch = 96;
    } else {
        int i = bid - 320; bx = 2 + (i & 3); by = i >> 2;
        A = xes; B = ball + (size_t)1024 * KEXT; C = kvenc; ldc = 768; nch = 48;
    }
    mma_body(sm, A + (size_t)by * 128 * KEXT, B + (size_t)bx * 128 * KEXT,
             C + (size_t)by * 128 * ldc + bx * 128, ldc, nch);
}

// cross-Q GEMM: split-K=2 over the 6 segments: half0 = [h,h,m], half1 = [h,l,m]
__global__ __launch_bounds__(256, 2) void crossq_k(
    const __nv_bfloat16* __restrict__ fxs, const __nv_bfloat16* __restrict__ ball,
    float* __restrict__ q2a, float* __restrict__ q2b)
{
    __shared__ SmemMM sm;
    const int bid = blockIdx.x;            // 128
    const int half = bid >> 6;
    const int i = bid & 63;
    const int bx = i & 1, by = i >> 1;
    const __nv_bfloat16* A = fxs + half * 1536;
    const __nv_bfloat16* B = ball + half * 1536;
    float* C = half ? q2b : q2a;
    mma_body(sm, A + (size_t)by * 128 * KEXT, B + (size_t)bx * 128 * KEXT,
             C + (size_t)by * 128 * 256 + bx * 128, 256, 48);
}

// ---------------- Attention v3: 2 queries/thread, online softmax ----------------
// Thread t handles queries q1=t and q2=t+256; K/V quads loaded once, used twice.
// Causal quirk preserved: m init 0 (masked zeros participate), masked V tail via
// suffix sums; in-loop causal mask via s=-1e30 select (ex2 -> exact 0).
template <int CAUSAL, int QSUM, int WSPLIT>
__global__ __launch_bounds__(256, 2) void attn3_k(
    const float* __restrict__ Qbuf, const float* __restrict__ Qbuf2, int ldq, int qoff,
    const float* __restrict__ KVbuf, int ldkv, int koff, int voff,
    float* __restrict__ Out, __nv_bfloat16* __restrict__ OutS)
{
    __shared__ float sKt[4][512];                 // K transposed: [dim][key]
    __shared__ __align__(16) float sV[512 * 8];   // V row-major:  [key][dim]
    __shared__ float sWS[8][8];                   // warp totals for suffix scans

    const int bh = blockIdx.x;
    const int h = bh & 63, b = bh >> 6;
    const int t = threadIdx.x, lane = t & 31, wid = t >> 5;

    float vown1[8], vown2[8];
#pragma unroll
    for (int rr = 0; rr < 2; rr++) {
        const int row = t + rr * 256;
        const float* kv = KVbuf + (size_t)(b * SEQ + row) * ldkv;
        float4 kk = *(const float4*)(kv + koff + h * 4);
        sKt[0][row] = kk.x; sKt[1][row] = kk.y; sKt[2][row] = kk.z; sKt[3][row] = kk.w;
        float4 v0 = *(const float4*)(kv + voff + h * 8);
        float4 v1 = *(const float4*)(kv + voff + h * 8 + 4);
        *(float4*)&sV[row * 8] = v0;
        *(float4*)&sV[row * 8 + 4] = v1;
        float* vo = rr ? vown2 : vown1;
        vo[0] = v0.x; vo[1] = v0.y; vo[2] = v0.z; vo[3] = v0.w;
        vo[4] = v1.x; vo[5] = v1.y; vo[6] = v1.z; vo[7] = v1.w;
    }

    float suf1[8], suf2[8];
    if (CAUSAL) {
        // half1 scan (rows 256..511): suf2[t] = sum_{k >= t+256} V[k]
#pragma unroll
        for (int d = 0; d < 8; d++) suf2[d] = vown2[d];
#pragma unroll
        for (int off = 1; off < 32; off <<= 1)
#pragma unroll
            for (int d = 0; d < 8; d++) {
                float o = __shfl_down_sync(0xffffffffu, suf2[d], off);
                if (lane + off < 32) suf2[d] += o;
            }
        if (lane == 0)
#pragma unroll
            for (int d = 0; d < 8; d++) sWS[wid][d] = suf2[d];
        __syncthreads();
        float tot2[8];
#pragma unroll
        for (int d = 0; d < 8; d++) {
            tot2[d] = 0.f;
#pragma unroll
            for (int w = 0; w < 8; w++) tot2[d] += sWS[w][d];
        }
        for (int w = wid + 1; w < 8; w++)
#pragma unroll
            for (int d = 0; d < 8; d++) suf2[d] += sWS[w][d];
        __syncthreads();
        // half0 scan (rows 0..255): suf1[t] = sum_{k >= t} + total(half1)
#pragma unroll
        for (int d = 0; d < 8; d++) suf1[d] = vown1[d];
#pragma unroll
        for (int off = 1; off < 32; off <<= 1)
#pragma unroll
            for (int d = 0; d < 8; d++) {
                float o = __shfl_down_sync(0xffffffffu, suf1[d], off);
                if (lane + off < 32) suf1[d] += o;
            }
        if (lane == 0)
#pragma unroll
            for (int d = 0; d < 8; d++) sWS[wid][d] = suf1[d];
        __syncthreads();
        for (int w = wid + 1; w < 8; w++)
#pragma unroll
            for (int d = 0; d < 8; d++) suf1[d] += sWS[w][d];
#pragma unroll
        for (int d = 0; d < 8; d++) {
            suf1[d] += tot2[d] - vown1[d];   // strict suffix k > q1
            suf2[d] -= vown2[d];             // strict suffix k > q2
        }
    } else {
        __syncthreads();
    }

    const float SCQ = 0.72134752044448170f;  // 0.5 * log2(e)
    unsigned long long aq1[4], aq2[4];
#pragma unroll
    for (int rr = 0; rr < 2; rr++) {
        const size_t row = (size_t)(b * SEQ + t + rr * 256);
        float4 qv = *(const float4*)(Qbuf + row * ldq + qoff + h * 4);
        if (QSUM) {
            float4 q2v = *(const float4*)(Qbuf2 + row * ldq + qoff + h * 4);
            qv.x += q2v.x; qv.y += q2v.y; qv.z += q2v.z; qv.w += q2v.w;
        }
        unsigned long long* aq = rr ? aq2 : aq1;
        aq[0] = pk2(qv.x * SCQ, qv.x * SCQ);
        aq[1] = pk2(qv.y * SCQ, qv.y * SCQ);
        aq[2] = pk2(qv.z * SCQ, qv.z * SCQ);
        aq[3] = pk2(qv.w * SCQ, qv.w * SCQ);
    }

    float m1 = CAUSAL ? 0.f : -1e30f, m2 = m1;
    float d1 = 0.f, d2 = 0.f;
    unsigned long long A1[4] = {0ULL, 0ULL, 0ULL, 0ULL};
    unsigned long long A2[4] = {0ULL, 0ULL, 0ULL, 0ULL};

    // per-quad online step for one query (V quad preloaded in vv)
    auto step = [&](const float* s, float& m, float& dn, unsigned long long* A,
                    const ulonglong2* vv) {
        float qm = fmaxf(fmaxf(s[0], s[1]), fmaxf(s[2], s[3]));
        if (qm > m) {
            float r = ex2(m - qm);
            m = qm; dn *= r;
            unsigned long long R = pk2(r, r);
            mul2(A[0], R); mul2(A[1], R); mul2(A[2], R); mul2(A[3], R);
        }
        float p0 = ex2(s[0] - m), p1 = ex2(s[1] - m);
        float p2 = ex2(s[2] - m), p3 = ex2(s[3] - m);
        dn += (p0 + p1) + (p2 + p3);
        unsigned long long P;
        P = pk2(p0, p0);
        fma2(A[0], P, vv[0].x); fma2(A[1], P, vv[0].y); fma2(A[2], P, vv[1].x); fma2(A[3], P, vv[1].y);
        P = pk2(p1, p1);
        fma2(A[0], P, vv[2].x); fma2(A[1], P, vv[2].y); fma2(A[2], P, vv[3].x); fma2(A[3], P, vv[3].y);
        P = pk2(p2, p2);
        fma2(A[0], P, vv[4].x); fma2(A[1], P, vv[4].y); fma2(A[2], P, vv[5].x); fma2(A[3], P, vv[5].y);
        P = pk2(p3, p3);
        fma2(A[0], P, vv[6].x); fma2(A[1], P, vv[6].y); fma2(A[2], P, vv[7].x); fma2(A[3], P, vv[7].y);
    };

    auto loadKV = [&](int k4, ulonglong2* kq, ulonglong2* vv) {
        kq[0] = *(const ulonglong2*)&sKt[0][k4];
        kq[1] = *(const ulonglong2*)&sKt[1][k4];
        kq[2] = *(const ulonglong2*)&sKt[2][k4];
        kq[3] = *(const ulonglong2*)&sKt[3][k4];
        const float* vb = &sV[k4 * 8];
#pragma unroll
        for (int j = 0; j < 4; j++) {
            vv[2 * j]     = *(const ulonglong2*)(vb + j * 8);
            vv[2 * j + 1] = *(const ulonglong2*)(vb + j * 8 + 4);
        }
    };

    auto scores = [&](const unsigned long long* aq, const ulonglong2* kq, float* s) {
        unsigned long long s01 = 0ULL, s23 = 0ULL;
        fma2(s01, aq[0], kq[0].x); fma2(s23, aq[0], kq[0].y);
        fma2(s01, aq[1], kq[1].x); fma2(s23, aq[1], kq[1].y);
        fma2(s01, aq[2], kq[2].x); fma2(s23, aq[2], kq[2].y);
        fma2(s01, aq[3], kq[3].x); fma2(s23, aq[3], kq[3].y);
        float2 f01 = up2(s01), f23 = up2(s23);
        s[0] = f01.x; s[1] = f01.y; s[2] = f23.x; s[3] = f23.y;
    };

    if (CAUSAL) {
        const int q1 = t, q2 = t + 256;
        const int nq1 = (q1 + 4) >> 2;   // quads covering keys 0..q1
        const int nq2 = (q2 + 4) >> 2;   // quads covering keys 0..q2
        for (int i = 0; i < nq1; i++) {
            const int k4 = i << 2;
            ulonglong2 kq[4], vv[8];
            loadKV(k4, kq, vv);
            float s1[4], s2[4];
            scores(aq1, kq, s1);
            scores(aq2, kq, s2);
#pragma unroll
            for (int j = 0; j < 4; j++) if (k4 + j > q1) s1[j] = -1e30f;
            step(s1, m1, d1, A1, vv);
            step(s2, m2, d2, A2, vv);
        }
        for (int i = nq1; i < nq2; i++) {
            const int k4 = i << 2;
            ulonglong2 kq[4], vv[8];
            loadKV(k4, kq, vv);
            float s2[4];
            scores(aq2, kq, s2);
#pragma unroll
            for (int j = 0; j < 4; j++) if (k4 + j > q2) s2[j] = -1e30f;
            step(s2, m2, d2, A2, vv);
        }
        // masked-zero tails (weight ex2(-m) per masked key, V via suffix sums)
        {
            float pm = ex2(-m1);
            d1 += (float)(SEQ - 1 - q1) * pm;
            unsigned long long P = pk2(pm, pm);
            fma2(A1[0], P, pk2(suf1[0], suf1[1]));
            fma2(A1[1], P, pk2(suf1[2], suf1[3]));
            fma2(A1[2], P, pk2(suf1[4], suf1[5]));
            fma2(A1[3], P, pk2(suf1[6], suf1[7]));
        }
        {
            float pm = ex2(-m2);
            d2 += (float)(SEQ - 1 - q2) * pm;
            unsigned long long P = pk2(pm, pm);
            fma2(A2[0], P, pk2(suf2[0], suf2[1]));
            fma2(A2[1], P, pk2(suf2[2], suf2[3]));
            fma2(A2[2], P, pk2(suf2[4], suf2[5]));
            fma2(A2[3], P, pk2(suf2[6], suf2[7]));
        }
    } else {
        for (int i = 0; i < 128; i++) {
            const int k4 = i << 2;
            ulonglong2 kq[4], vv[8];
            loadKV(k4, kq, vv);
            float s1[4], s2[4];
            scores(aq1, kq, s1);
            scores(aq2, kq, s2);
            step(s1, m1, d1, A1, vv);
            step(s2, m2, d2, A2, vv);
        }
    }

    // epilogue for both queries
#pragma unroll
    for (int rr = 0; rr < 2; rr++) {
        const unsigned long long* A = rr ? A2 : A1;
        const float inv = 1.0f / (rr ? d2 : d1);
        float2 o0 = up2(A[0]), o1 = up2(A[1]), o2 = up2(A[2]), o3 = up2(A[3]);
        float vals[8] = {o0.x * inv, o0.y * inv, o1.x * inv, o1.y * inv,
                         o2.x * inv, o2.y * inv, o3.x * inv, o3.y * inv};
        const size_t rowbase = (size_t)(b * SEQ + t + rr * 256);
        if (WSPLIT) {
            __align__(16) __nv_bfloat16 H[8], M[8], L[8];
#pragma unroll
            for (int d = 0; d < 8; d++) split3(vals[d], H[d], M[d], L[d]);
            __nv_bfloat16* ob = OutS + rowbase * KEXT + h * 8;
            *(uint4*)(ob)        = *(uint4*)H;
            *(uint4*)(ob + 512)  = *(uint4*)H;
            *(uint4*)(ob + 1024) = *(uint4*)M;
            *(uint4*)(ob + 1536) = *(uint4*)H;
            *(uint4*)(ob + 2048) = *(uint4*)L;
            *(uint4*)(ob + 2560) = *(uint4*)M;
        } else {
            float* o = Out + rowbase * DM + h * 8;
            *(float4*)(o)     = make_float4(vals[0], vals[1], vals[2], vals[3]);
            *(float4*)(o + 4) = make_float4(vals[4], vals[5], vals[6], vals[7]);
        }
    }
}

// ---------------- Residual + LayerNorm + FFN (hidden=10) fused ----------------
#define HIDD 10
__global__ __launch_bounds__(256) void lnffn_k(
    const float* __restrict__ x, const float* __restrict__ fx,
    const float* __restrict__ lg, const float* __restrict__ lb,
    const float* __restrict__ w1, const float* __restrict__ b1,
    const float* __restrict__ w2, const float* __restrict__ b2,
    float* __restrict__ out)
{
    const int row = blockIdx.x;
    const int t = threadIdx.x;
    const int warp = t >> 5, lane = t & 31;

    const float* xr = x + row * DM;
    const float* fr = fx + row * DM;
    float v0 = xr[t] + fr[t];
    float v1 = xr[t + 256] + fr[t + 256];

    float s = v0 + v1;
    float ss = v0 * v0 + v1 * v1;
#pragma unroll
    for (int o = 16; o > 0; o >>= 1) {
        s  += __shfl_down_sync(0xffffffffu, s,  o);
        ss += __shfl_down_sync(0xffffffffu, ss, o);
    }
    __shared__ float rs[8], rss[8];
    if (lane == 0) { rs[warp] = s; rss[warp] = ss; }
    __syncthreads();
    float S = 0.f, SS = 0.f;
#pragma unroll
    for (int w = 0; w < 8; w++) { S += rs[w]; SS += rss[w]; }
    const float mu = S * (1.0f / DM);
    const float var = SS * (1.0f / DM) - mu * mu;
    const float rstd = rsqrtf(var + 1e-5f);

    const float y0 = (v0 - mu) * rstd * lg[t] + lb[t];
    const float y1 = (v1 - mu) * rstd * lg[t + 256] + lb[t + 256];

    float pj[HIDD];
#pragma unroll
    for (int j = 0; j < HIDD; j++)
        pj[j] = y0 * __ldg(&w1[j * DM + t]) + y1 * __ldg(&w1[j * DM + t + 256]);
#pragma unroll
    for (int j = 0; j < HIDD; j++)
#pragma unroll
        for (int o = 16; o > 0; o >>= 1)
            pj[j] += __shfl_down_sync(0xffffffffu, pj[j], o);

    __shared__ float hred[8][HIDD];
    if (lane == 0)
#pragma unroll
        for (int j = 0; j < HIDD; j++) hred[warp][j] = pj[j];
    __syncthreads();

    __shared__ float sh[HIDD];
    if (t < HIDD) {
        float hv = b1[t];
#pragma unroll
        for (int w = 0; w < 8; w++) hv += hred[w][t];
        sh[t] = fmaxf(hv, 0.f);
    }
    __syncthreads();

    float o0 = b2[t], o1 = b2[t + 256];
#pragma unroll
    for (int j = 0; j < HIDD; j++) {
        const float hj = sh[j];
        o0 = fmaf(hj, __ldg(&w2[t * HIDD + j]), o0);
        o1 = fmaf(hj, __ldg(&w2[(t + 256) * HIDD + j]), o1);
    }
    out[row * DM + t] = o0;
    out[row * DM + t + 256] = o1;
}

// ---------------- launch ----------------
extern "C" void kernel_launch(void* const* d_in, const int* in_sizes, int n_in,
                              void* d_out, int out_size)
{
    const float* x   = (const float*)d_in[0];
    const float* xe  = (const float*)d_in[1];
    const float* Wq  = (const float*)d_in[2];
    const float* Wk  = (const float*)d_in[3];
    const float* Wv  = (const float*)d_in[4];
    const float* lg  = (const float*)d_in[5];
    const float* lb  = (const float*)d_in[6];
    const float* w1  = (const float*)d_in[7];
    const float* b1  = (const float*)d_in[8];
    const float* w2  = (const float*)d_in[9];
    const float* b2  = (const float*)d_in[10];
    float* out = (float*)d_out;

    float *qkv, *kvenc, *q2a, *q2b, *fx2;
    __nv_bfloat16 *xs, *xes, *fxs, *ball;
    cudaGetSymbolAddress((void**)&qkv,   g_qkv);
    cudaGetSymbolAddress((void**)&kvenc, g_kvenc);
    cudaGetSymbolAddress((void**)&q2a,   g_q2a);
    cudaGetSymbolAddress((void**)&q2b,   g_q2b);
    cudaGetSymbolAddress((void**)&fx2,   g_fx2);
    cudaGetSymbolAddress((void**)&xs,    g_xs);
    cudaGetSymbolAddress((void**)&xes,   g_xes);
    cudaGetSymbolAddress((void**)&fxs,   g_fxs);
    cudaGetSymbolAddress((void**)&ball,  g_ball);

    // split inputs + weights into 6-segment bf16 K-extension
    splitAB_k<<<16384, 256>>>(x, xe, xs, xes);
    splitW_k<<<dim3(16, 56), dim3(32, 8)>>>(Wq, Wk, Wv, ball);

    // fused projections (heavy 6-limb tiles first; enc-V 3-limb tiles last)
    proj_k<<<448, 256>>>(xs, xes, ball, qkv, kvenc);

    // self-attention; writes split-extended fxs directly
    attn3_k<1, 0, 1><<<512, 256>>>(qkv, nullptr, 1024, 0, qkv, 1024, 256, 512, nullptr, fxs);

    // cross-attention Q projection (split-K=2 over segment halves)
    crossq_k<<<128, 256>>>(fxs, ball, q2a, q2b);

    // cross-attention (no mask), Q = q2a + q2b
    attn3_k<0, 1, 0><<<512, 256>>>(q2a, q2b, 256, 0, kvenc, 768, 0, 256, fx2, nullptr);

    // residual + LN + FFN
    lnffn_k<<<4096, 256>>>(x, fx2, lg, lb, w1, b1, w2, b2, out);
}

// round 8
// speedup vs baseline: 1.8665x; 1.0030x over previous
#include <cuda_runtime.h>
#include <cuda_bf16.h>
#include <cstdint>

#define BS 8
#define SEQ 512
#define DM 512
#define NROW (BS*SEQ)          // 4096
#define KEXT 3072              // 6 segments x 512

// ---------------- scratch (no allocation allowed) ----------------
__device__ __align__(16) float g_qkv[NROW * 1024];    // [Q(256)|K(256)|V(512)] self
__device__ __align__(16) float g_kvenc[NROW * 768];   // [K(256)|V(512)] encoder
__device__ __align__(16) float g_q2a[NROW * 256];     // cross-Q split-K partial 0
__device__ __align__(16) float g_q2b[NROW * 256];     // cross-Q split-K partial 1
__device__ __align__(16) float g_fx2[NROW * 512];     // cross-attn output
__device__ __align__(16) __nv_bfloat16 g_xs [NROW * KEXT];   // x   split-extended
__device__ __align__(16) __nv_bfloat16 g_xes[NROW * KEXT];   // xe  split-extended
__device__ __align__(16) __nv_bfloat16 g_fxs[NROW * KEXT];   // fx  split-extended
__device__ __align__(16) __nv_bfloat16 g_ball[1792 * KEXT];  // [Wq|Wk|Wv|Wk|Wv]^T split

// ---------------- helpers ----------------
__device__ __forceinline__ uint32_t smem_u32(const void* p) {
    uint32_t a;
    asm("{ .reg .u64 t; cvta.to.shared.u64 t, %1; cvt.u32.u64 %0, t; }" : "=r"(a) : "l"(p));
    return a;
}
__device__ __forceinline__ float ex2(float x) {
    float y; asm("ex2.approx.f32 %0, %1;" : "=f"(y) : "f"(x)); return y;
}
__device__ __forceinline__ unsigned long long pk2(float x, float y) {
    unsigned long long r; asm("mov.b64 %0, {%1,%2};" : "=l"(r) : "f"(x), "f"(y)); return r;
}
__device__ __forceinline__ void fma2(unsigned long long& d, unsigned long long a, unsigned long long b) {
    asm("fma.rn.f32x2 %0, %1, %2, %0;" : "+l"(d) : "l"(a), "l"(b));
}
__device__ __forceinline__ void mul2(unsigned long long& d, unsigned long long a) {
    asm("mul.rn.f32x2 %0, %0, %1;" : "+l"(d) : "l"(a));
}
__device__ __forceinline__ float2 up2(unsigned long long v) {
    float2 r; asm("mov.b64 {%0,%1}, %2;" : "=f"(r.x), "=f"(r.y) : "l"(v)); return r;
}
__device__ __forceinline__ void cpasync16(uint32_t dst, const void* src) {
    asm volatile("cp.async.cg.shared.global [%0], [%1], 16;" :: "r"(dst), "l"(src));
}

__device__ __forceinline__ void split3(float v, __nv_bfloat16& h, __nv_bfloat16& m, __nv_bfloat16& l) {
    h = __float2bfloat16(v);
    float r1 = v - __bfloat162float(h);
    m = __float2bfloat16(r1);
    float r2 = r1 - __bfloat162float(m);
    l = __float2bfloat16(r2);
}

// ---------------- split kernels ----------------
// A segments: [hi, hi, mid, hi, lo, mid]; handles x and xe in one launch.
__global__ __launch_bounds__(256) void splitAB_k(const float* __restrict__ x, const float* __restrict__ xe,
                                                 __nv_bfloat16* __restrict__ xs, __nv_bfloat16* __restrict__ xes)
{
    int gid = blockIdx.x * 256 + threadIdx.x;   // 2 * NROW*512
    const float* in; __nv_bfloat16* out; int id;
    if (gid < NROW * 512) { in = x; out = xs; id = gid; }
    else { in = xe; out = xes; id = gid - NROW * 512; }
    int r = id >> 9, c = id & 511;
    __nv_bfloat16 h, m, l;
    split3(in[id], h, m, l);
    __nv_bfloat16* o = out + (size_t)r * KEXT + c;
    o[0] = h; o[512] = h; o[1024] = m; o[1536] = h; o[2048] = l; o[2560] = m;
}

// B rows: g_ball[n][k] = W[k][n], segments [hi, mid, hi, lo, hi, mid]
__global__ void splitW_k(const float* __restrict__ Wq, const float* __restrict__ Wk,
                         const float* __restrict__ Wv, __nv_bfloat16* __restrict__ out)
{
    __shared__ float s[32][33];
    const int k0 = blockIdx.x * 32, n0 = blockIdx.y * 32;
    const int tx = threadIdx.x, ty = threadIdx.y;   // 32 x 8

    const float* src; int col0, ldw;
    if      (n0 < 256)  { src = Wq; col0 = n0;        ldw = 256; }
    else if (n0 < 512)  { src = Wk; col0 = n0 - 256;  ldw = 256; }
    else if (n0 < 1024) { src = Wv; col0 = n0 - 512;  ldw = 512; }
    else if (n0 < 1280) { src = Wk; col0 = n0 - 1024; ldw = 256; }
    else                { src = Wv; col0 = n0 - 1280; ldw = 512; }

#pragma unroll
    for (int i = 0; i < 4; i++) {
        int kk = ty + i * 8;
        s[kk][tx] = src[(k0 + kk) * ldw + col0 + tx];
    }
    __syncthreads();
#pragma unroll
    for (int i = 0; i < 4; i++) {
        int nn = ty + i * 8;
        __nv_bfloat16 h, m, l;
        split3(s[tx][nn], h, m, l);
        __nv_bfloat16* o = out + (size_t)(n0 + nn) * KEXT + k0 + tx;
        o[0] = h; o[512] = m; o[1024] = h; o[1536] = l; o[2048] = h; o[2560] = m;
    }
}

// ---------------- mma.sync GEMM body: 128x128 CTA tile, runtime K ----------------
struct SmemMM {
    __nv_bfloat16 sA[2][128][40];   // 40 = 32 + pad (conflict-free)
    __nv_bfloat16 sB[2][128][40];
};

__device__ __forceinline__ void mma_body(SmemMM& sm,
    const __nv_bfloat16* __restrict__ A, const __nv_bfloat16* __restrict__ B,
    float* __restrict__ C, int ldc, int nch)
{
    const int tid = threadIdx.x;
    const int wid = tid >> 5, lane = tid & 31;

    const uint32_t sAb = smem_u32(&sm.sA[0][0][0]);
    const uint32_t sBb = smem_u32(&sm.sB[0][0][0]);
    const uint32_t STAGE = 128 * 80;

    auto issue = [&](int c, int buf) {
#pragma unroll
        for (int i = 0; i < 2; i++) {
            int g = tid + i * 256;
            int r = g >> 2, j = g & 3;
            uint32_t so = (uint32_t)buf * STAGE + r * 80 + j * 16;
            cpasync16(sAb + so, (const char*)(A + (size_t)r * KEXT + c * 32 + j * 8));
            cpasync16(sBb + so, (const char*)(B + (size_t)r * KEXT + c * 32 + j * 8));
        }
    };

    issue(0, 0);
    asm volatile("cp.async.commit_group;" ::: "memory");
    issue(1, 1);
    asm volatile("cp.async.commit_group;" ::: "memory");

    float acc[4][4][4];
#pragma unroll
    for (int i = 0; i < 4; i++)
#pragma unroll
        for (int j = 0; j < 4; j++)
#pragma unroll
            for (int k = 0; k < 4; k++) acc[i][j][k] = 0.f;

    const int wm = wid >> 2, wn = wid & 3;
    const int rbase = wm * 64 + (lane >> 2);
    const int nbase = wn * 32 + (lane >> 2);
    const int lq = lane & 3;

    for (int c = 0; c < nch; c++) {
        asm volatile("cp.async.wait_group 1;" ::: "memory");
        __syncthreads();
        const uint32_t* sA32 = (const uint32_t*)&sm.sA[c & 1][0][0];
        const uint32_t* sB32 = (const uint32_t*)&sm.sB[c & 1][0][0];

#pragma unroll
        for (int ks = 0; ks < 2; ks++) {
            const int cw = ks * 8 + lq;
            uint32_t af[4][4], bf[4][2];
#pragma unroll
            for (int am = 0; am < 4; am++) {
                int r = rbase + am * 16;
                af[am][0] = sA32[r * 20 + cw];
                af[am][1] = sA32[(r + 8) * 20 + cw];
                af[am][2] = sA32[r * 20 + cw + 4];
                af[am][3] = sA32[(r + 8) * 20 + cw + 4];
            }
#pragma unroll
            for (int an = 0; an < 4; an++) {
                int n = nbase + an * 8;
                bf[an][0] = sB32[n * 20 + cw];
                bf[an][1] = sB32[n * 20 + cw + 4];
            }
#pragma unroll
            for (int am = 0; am < 4; am++)
#pragma unroll
                for (int an = 0; an < 4; an++) {
                    asm volatile(
                        "mma.sync.aligned.m16n8k16.row.col.f32.bf16.bf16.f32 "
                        "{%0,%1,%2,%3}, {%4,%5,%6,%7}, {%8,%9}, {%0,%1,%2,%3};"
                        : "+f"(acc[am][an][0]), "+f"(acc[am][an][1]),
                          "+f"(acc[am][an][2]), "+f"(acc[am][an][3])
                        : "r"(af[am][0]), "r"(af[am][1]), "r"(af[am][2]), "r"(af[am][3]),
                          "r"(bf[an][0]), "r"(bf[an][1]));
                }
        }
        __syncthreads();
        if (c + 2 < nch) issue(c + 2, c & 1);
        asm volatile("cp.async.commit_group;" ::: "memory");
    }

#pragma unroll
    for (int am = 0; am < 4; am++) {
#pragma unroll
        for (int an = 0; an < 4; an++) {
            int r0 = wm * 64 + am * 16 + (lane >> 2);
            int cc = wn * 32 + an * 8 + lq * 2;
            *(float2*)&C[r0 * ldc + cc]       = make_float2(acc[am][an][0], acc[am][an][1]);
            *(float2*)&C[(r0 + 8) * ldc + cc] = make_float2(acc[am][an][2], acc[am][an][3]);
        }
    }
}

// fused projections, 448 blocks, heavy (6-limb) first, light (3-limb enc-V) last
__global__ __launch_bounds__(256, 2) void proj_k(
    const __nv_bfloat16* __restrict__ xs, const __nv_bfloat16* __restrict__ xes,
    const __nv_bfloat16* __restrict__ ball, float* __restrict__ qkv, float* __restrict__ kvenc)
{
    __shared__ SmemMM sm;
    const int bid = blockIdx.x;
    const __nv_bfloat16 *A, *B; float* C; int ldc, nch, bx, by;
    if (bid < 256) {
        bx = bid & 7; by = bid >> 3;
        A = xs; B = ball; C = qkv; ldc = 1024; nch = 96;
    } else if (bid < 320) {
        int i = bid - 256; bx = i & 1; by = i >> 1;
        A = xes; B = ball + (size_t)1024 * KEXT; C = kvenc; ldc = 768; nch = 96;
    } else {
        int i = bid - 320; bx = 2 + (i & 3); by = i >> 2;
        A = xes; B = ball + (size_t)1024 * KEXT; C = kvenc; ldc = 768; nch = 48;
    }
    mma_body(sm, A + (size_t)by * 128 * KEXT, B + (size_t)bx * 128 * KEXT,
             C + (size_t)by * 128 * ldc + bx * 128, ldc, nch);
}

// cross-Q GEMM: split-K=2 over the 6 segments: half0 = [h,h,m], half1 = [h,l,m]
__global__ __launch_bounds__(256, 2) void crossq_k(
    const __nv_bfloat16* __restrict__ fxs, const __nv_bfloat16* __restrict__ ball,
    float* __restrict__ q2a, float* __restrict__ q2b)
{
    __shared__ SmemMM sm;
    const int bid = blockIdx.x;            // 128
    const int half = bid >> 6;
    const int i = bid & 63;
    const int bx = i & 1, by = i >> 1;
    const __nv_bfloat16* A = fxs + half * 1536;
    const __nv_bfloat16* B = ball + half * 1536;
    float* C = half ? q2b : q2a;
    mma_body(sm, A + (size_t)by * 128 * KEXT, B + (size_t)bx * 128 * KEXT,
             C + (size_t)by * 128 * 256 + bx * 128, 256, 48);
}

// ---------------- Attention v4: balanced 2 queries/thread, online softmax ----------------
// CAUSAL: thread t handles q1=t and q2=511-t so per-thread instruction cost is
// constant and per-warp spread is ~1.12x (vs 2.2x with t,t+256). Strict V suffix
// sums for arbitrary q come from a full smem suffix array sSuf[513][8].
// Masked-zero softmax quirk preserved exactly.
template <int CAUSAL, int QSUM, int WSPLIT>
__global__ __launch_bounds__(256, 2) void attn4_k(
    const float* __restrict__ Qbuf, const float* __restrict__ Qbuf2, int ldq, int qoff,
    const float* __restrict__ KVbuf, int ldkv, int koff, int voff,
    float* __restrict__ Out, __nv_bfloat16* __restrict__ OutS)
{
    __shared__ float sKt[4][512];                 // K transposed: [dim][key]
    __shared__ __align__(16) float sV[512 * 8];   // V row-major:  [key][dim]
    __shared__ __align__(16) float sSuf[513][8];  // inclusive V suffix sums (causal)
    __shared__ float sWS[16][8];                  // segment totals for suffix scan

    const int bh = blockIdx.x;
    const int h = bh & 63, b = bh >> 6;
    const int t = threadIdx.x, lane = t & 31, wid = t >> 5;

    const int q1 = t;
    const int q2 = CAUSAL ? (511 - t) : (t + 256);

    float vown[2][8];
#pragma unroll
    for (int rr = 0; rr < 2; rr++) {
        const int row = t + rr * 256;
        const float* kv = KVbuf + (size_t)(b * SEQ + row) * ldkv;
        float4 kk = *(const float4*)(kv + koff + h * 4);
        sKt[0][row] = kk.x; sKt[1][row] = kk.y; sKt[2][row] = kk.z; sKt[3][row] = kk.w;
        float4 v0 = *(const float4*)(kv + voff + h * 8);
        float4 v1 = *(const float4*)(kv + voff + h * 8 + 4);
        *(float4*)&sV[row * 8] = v0;
        *(float4*)&sV[row * 8 + 4] = v1;
        vown[rr][0] = v0.x; vown[rr][1] = v0.y; vown[rr][2] = v0.z; vown[rr][3] = v0.w;
        vown[rr][4] = v1.x; vown[rr][5] = v1.y; vown[rr][6] = v1.z; vown[rr][7] = v1.w;
    }

    if (CAUSAL) {
        // inclusive warp-suffix scans for rows t (segment wid) and t+256 (segment wid+8)
        float sc[2][8];
#pragma unroll
        for (int rr = 0; rr < 2; rr++) {
#pragma unroll
            for (int d = 0; d < 8; d++) sc[rr][d] = vown[rr][d];
#pragma unroll
            for (int off = 1; off < 32; off <<= 1)
#pragma unroll
                for (int d = 0; d < 8; d++) {
                    float o = __shfl_down_sync(0xffffffffu, sc[rr][d], off);
                    if (lane + off < 32) sc[rr][d] += o;
                }
            if (lane == 0)
#pragma unroll
                for (int d = 0; d < 8; d++) sWS[rr * 8 + wid][d] = sc[rr][d];
        }
        __syncthreads();
#pragma unroll
        for (int rr = 0; rr < 2; rr++) {
            const int seg = rr * 8 + wid;
            for (int s = seg + 1; s < 16; s++)
#pragma unroll
                for (int d = 0; d < 8; d++) sc[rr][d] += sWS[s][d];
            float* dst = sSuf[t + rr * 256];
            *(float4*)(dst)     = make_float4(sc[rr][0], sc[rr][1], sc[rr][2], sc[rr][3]);
            *(float4*)(dst + 4) = make_float4(sc[rr][4], sc[rr][5], sc[rr][6], sc[rr][7]);
        }
        if (t == 0) {
            *(float4*)(sSuf[512])     = make_float4(0.f, 0.f, 0.f, 0.f);
            *(float4*)(sSuf[512] + 4) = make_float4(0.f, 0.f, 0.f, 0.f);
        }
    }
    __syncthreads();

    const float SCQ = 0.72134752044448170f;  // 0.5 * log2(e)
    unsigned long long aq1[4], aq2[4];
#pragma unroll
    for (int rr = 0; rr < 2; rr++) {
        const size_t row = (size_t)(b * SEQ + (rr ? q2 : q1));
        float4 qv = *(const float4*)(Qbuf + row * ldq + qoff + h * 4);
        if (QSUM) {
            float4 q2v = *(const float4*)(Qbuf2 + row * ldq + qoff + h * 4);
            qv.x += q2v.x; qv.y += q2v.y; qv.z += q2v.z; qv.w += q2v.w;
        }
        unsigned long long* aq = rr ? aq2 : aq1;
        aq[0] = pk2(qv.x * SCQ, qv.x * SCQ);
        aq[1] = pk2(qv.y * SCQ, qv.y * SCQ);
        aq[2] = pk2(qv.z * SCQ, qv.z * SCQ);
        aq[3] = pk2(qv.w * SCQ, qv.w * SCQ);
    }

    float m1 = CAUSAL ? 0.f : -1e30f, m2 = m1;
    float d1 = 0.f, d2 = 0.f;
    unsigned long long A1[4] = {0ULL, 0ULL, 0ULL, 0ULL};
    unsigned long long A2[4] = {0ULL, 0ULL, 0ULL, 0ULL};

    auto step = [&](const float* s, float& m, float& dn, unsigned long long* A,
                    const ulonglong2* vv) {
        float qm = fmaxf(fmaxf(s[0], s[1]), fmaxf(s[2], s[3]));
        if (qm > m) {
            float r = ex2(m - qm);
            m = qm; dn *= r;
            unsigned long long R = pk2(r, r);
            mul2(A[0], R); mul2(A[1], R); mul2(A[2], R); mul2(A[3], R);
        }
        float p0 = ex2(s[0] - m), p1 = ex2(s[1] - m);
        float p2 = ex2(s[2] - m), p3 = ex2(s[3] - m);
        dn += (p0 + p1) + (p2 + p3);
        unsigned long long P;
        P = pk2(p0, p0);
        fma2(A[0], P, vv[0].x); fma2(A[1], P, vv[0].y); fma2(A[2], P, vv[1].x); fma2(A[3], P, vv[1].y);
        P = pk2(p1, p1);
        fma2(A[0], P, vv[2].x); fma2(A[1], P, vv[2].y); fma2(A[2], P, vv[3].x); fma2(A[3], P, vv[3].y);
        P = pk2(p2, p2);
        fma2(A[0], P, vv[4].x); fma2(A[1], P, vv[4].y); fma2(A[2], P, vv[5].x); fma2(A[3], P, vv[5].y);
        P = pk2(p3, p3);
        fma2(A[0], P, vv[6].x); fma2(A[1], P, vv[6].y); fma2(A[2], P, vv[7].x); fma2(A[3], P, vv[7].y);
    };

    auto loadKV = [&](int k4, ulonglong2* kq, ulonglong2* vv) {
        kq[0] = *(const ulonglong2*)&sKt[0][k4];
        kq[1] = *(const ulonglong2*)&sKt[1][k4];
        kq[2] = *(const ulonglong2*)&sKt[2][k4];
        kq[3] = *(const ulonglong2*)&sKt[3][k4];
        const float* vb = &sV[k4 * 8];
#pragma unroll
        for (int j = 0; j < 4; j++) {
            vv[2 * j]     = *(const ulonglong2*)(vb + j * 8);
            vv[2 * j + 1] = *(const ulonglong2*)(vb + j * 8 + 4);
        }
    };

    auto scores = [&](const unsigned long long* aq, const ulonglong2* kq, float* s) {
        unsigned long long s01 = 0ULL, s23 = 0ULL;
        fma2(s01, aq[0], kq[0].x); fma2(s23, aq[0], kq[0].y);
        fma2(s01, aq[1], kq[1].x); fma2(s23, aq[1], kq[1].y);
        fma2(s01, aq[2], kq[2].x); fma2(s23, aq[2], kq[2].y);
        fma2(s01, aq[3], kq[3].x); fma2(s23, aq[3], kq[3].y);
        float2 f01 = up2(s01), f23 = up2(s23);
        s[0] = f01.x; s[1] = f01.y; s[2] = f23.x; s[3] = f23.y;
    };

    if (CAUSAL) {
        const int nqA = (q1 + 4) >> 2;   // quads covering keys 0..q1 (all keys <= 255 < q2)
        const int nqB = (q2 + 4) >> 2;   // quads covering keys 0..q2
        for (int i = 0; i < nqA; i++) {
            const int k4 = i << 2;
            ulonglong2 kq[4], vv[8];
            loadKV(k4, kq, vv);
            float s1[4], s2[4];
            scores(aq1, kq, s1);
            scores(aq2, kq, s2);
#pragma unroll
            for (int j = 0; j < 4; j++) if (k4 + j > q1) s1[j] = -1e30f;
            step(s1, m1, d1, A1, vv);
            step(s2, m2, d2, A2, vv);
        }
        for (int i = nqA; i < nqB; i++) {
            const int k4 = i << 2;
            ulonglong2 kq[4], vv[8];
            loadKV(k4, kq, vv);
            float s2[4];
            scores(aq2, kq, s2);
#pragma unroll
            for (int j = 0; j < 4; j++) if (k4 + j > q2) s2[j] = -1e30f;
            step(s2, m2, d2, A2, vv);
        }
        // masked-zero tails: weight ex2(-m) per masked key, V via strict suffix sums
        {
            const float* sf = sSuf[q1 + 1];
            float pm = ex2(-m1);
            d1 += (float)(SEQ - 1 - q1) * pm;
            unsigned long long P = pk2(pm, pm);
            fma2(A1[0], P, pk2(sf[0], sf[1]));
            fma2(A1[1], P, pk2(sf[2], sf[3]));
            fma2(A1[2], P, pk2(sf[4], sf[5]));
            fma2(A1[3], P, pk2(sf[6], sf[7]));
        }
        {
            const float* sf = sSuf[q2 + 1];
            float pm = ex2(-m2);
            d2 += (float)(SEQ - 1 - q2) * pm;
            unsigned long long P = pk2(pm, pm);
            fma2(A2[0], P, pk2(sf[0], sf[1]));
            fma2(A2[1], P, pk2(sf[2], sf[3]));
            fma2(A2[2], P, pk2(sf[4], sf[5]));
            fma2(A2[3], P, pk2(sf[6], sf[7]));
        }
    } else {
        for (int i = 0; i < 128; i++) {
            const int k4 = i << 2;
            ulonglong2 kq[4], vv[8];
            loadKV(k4, kq, vv);
            float s1[4], s2[4];
            scores(aq1, kq, s1);
            scores(aq2, kq, s2);
            step(s1, m1, d1, A1, vv);
            step(s2, m2, d2, A2, vv);
        }
    }

    // epilogue for both queries
#pragma unroll
    for (int rr = 0; rr < 2; rr++) {
        const unsigned long long* A = rr ? A2 : A1;
        const float inv = 1.0f / (rr ? d2 : d1);
        float2 o0 = up2(A[0]), o1 = up2(A[1]), o2 = up2(A[2]), o3 = up2(A[3]);
        float vals[8] = {o0.x * inv, o0.y * inv, o1.x * inv, o1.y * inv,
                         o2.x * inv, o2.y * inv, o3.x * inv, o3.y * inv};
        const size_t rowbase = (size_t)(b * SEQ + (rr ? q2 : q1));
        if (WSPLIT) {
            __align__(16) __nv_bfloat16 H[8], M[8], L[8];
#pragma unroll
            for (int d = 0; d < 8; d++) split3(vals[d], H[d], M[d], L[d]);
            __nv_bfloat16* ob = OutS + rowbase * KEXT + h * 8;
            *(uint4*)(ob)        = *(uint4*)H;
            *(uint4*)(ob + 512)  = *(uint4*)H;
            *(uint4*)(ob + 1024) = *(uint4*)M;
            *(uint4*)(ob + 1536) = *(uint4*)H;
            *(uint4*)(ob + 2048) = *(uint4*)L;
            *(uint4*)(ob + 2560) = *(uint4*)M;
        } else {
            float* o = Out + rowbase * DM + h * 8;
            *(float4*)(o)     = make_float4(vals[0], vals[1], vals[2], vals[3]);
            *(float4*)(o + 4) = make_float4(vals[4], vals[5], vals[6], vals[7]);
        }
    }
}

// ---------------- Residual + LayerNorm + FFN (hidden=10) fused ----------------
#define HIDD 10
__global__ __launch_bounds__(256) void lnffn_k(
    const float* __restrict__ x, const float* __restrict__ fx,
    const float* __restrict__ lg, const float* __restrict__ lb,
    const float* __restrict__ w1, const float* __restrict__ b1,
    const float* __restrict__ w2, const float* __restrict__ b2,
    float* __restrict__ out)
{
    const int row = blockIdx.x;
    const int t = threadIdx.x;
    const int warp = t >> 5, lane = t & 31;

    const float* xr = x + row * DM;
    const float* fr = fx + row * DM;
    float v0 = xr[t] + fr[t];
    float v1 = xr[t + 256] + fr[t + 256];

    float s = v0 + v1;
    float ss = v0 * v0 + v1 * v1;
#pragma unroll
    for (int o = 16; o > 0; o >>= 1) {
        s  += __shfl_down_sync(0xffffffffu, s,  o);
        ss += __shfl_down_sync(0xffffffffu, ss, o);
    }
    __shared__ float rs[8], rss[8];
    if (lane == 0) { rs[warp] = s; rss[warp] = ss; }
    __syncthreads();
    float S = 0.f, SS = 0.f;
#pragma unroll
    for (int w = 0; w < 8; w++) { S += rs[w]; SS += rss[w]; }
    const float mu = S * (1.0f / DM);
    const float var = SS * (1.0f / DM) - mu * mu;
    const float rstd = rsqrtf(var + 1e-5f);

    const float y0 = (v0 - mu) * rstd * lg[t] + lb[t];
    const float y1 = (v1 - mu) * rstd * lg[t + 256] + lb[t + 256];

    float pj[HIDD];
#pragma unroll
    for (int j = 0; j < HIDD; j++)
        pj[j] = y0 * __ldg(&w1[j * DM + t]) + y1 * __ldg(&w1[j * DM + t + 256]);
#pragma unroll
    for (int j = 0; j < HIDD; j++)
#pragma unroll
        for (int o = 16; o > 0; o >>= 1)
            pj[j] += __shfl_down_sync(0xffffffffu, pj[j], o);

    __shared__ float hred[8][HIDD];
    if (lane == 0)
#pragma unroll
        for (int j = 0; j < HIDD; j++) hred[warp][j] = pj[j];
    __syncthreads();

    __shared__ float sh[HIDD];
    if (t < HIDD) {
        float hv = b1[t];
#pragma unroll
        for (int w = 0; w < 8; w++) hv += hred[w][t];
        sh[t] = fmaxf(hv, 0.f);
    }
    __syncthreads();

    float o0 = b2[t], o1 = b2[t + 256];
#pragma unroll
    for (int j = 0; j < HIDD; j++) {
        const float hj = sh[j];
        o0 = fmaf(hj, __ldg(&w2[t * HIDD + j]), o0);
        o1 = fmaf(hj, __ldg(&w2[(t + 256) * HIDD + j]), o1);
    }
    out[row * DM + t] = o0;
    out[row * DM + t + 256] = o1;
}

// ---------------- launch ----------------
extern "C" void kernel_launch(void* const* d_in, const int* in_sizes, int n_in,
                              void* d_out, int out_size)
{
    const float* x   = (const float*)d_in[0];
    const float* xe  = (const float*)d_in[1];
    const float* Wq  = (const float*)d_in[2];
    const float* Wk  = (const float*)d_in[3];
    const float* Wv  = (const float*)d_in[4];
    const float* lg  = (const float*)d_in[5];
    const float* lb  = (const float*)d_in[6];
    const float* w1  = (const float*)d_in[7];
    const float* b1  = (const float*)d_in[8];
    const float* w2  = (const float*)d_in[9];
    const float* b2  = (const float*)d_in[10];
    float* out = (float*)d_out;

    float *qkv, *kvenc, *q2a, *q2b, *fx2;
    __nv_bfloat16 *xs, *xes, *fxs, *ball;
    cudaGetSymbolAddress((void**)&qkv,   g_qkv);
    cudaGetSymbolAddress((void**)&kvenc, g_kvenc);
    cudaGetSymbolAddress((void**)&q2a,   g_q2a);
    cudaGetSymbolAddress((void**)&q2b,   g_q2b);
    cudaGetSymbolAddress((void**)&fx2,   g_fx2);
    cudaGetSymbolAddress((void**)&xs,    g_xs);
    cudaGetSymbolAddress((void**)&xes,   g_xes);
    cudaGetSymbolAddress((void**)&fxs,   g_fxs);
    cudaGetSymbolAddress((void**)&ball,  g_ball);

    // split inputs + weights into 6-segment bf16 K-extension
    splitAB_k<<<16384, 256>>>(x, xe, xs, xes);
    splitW_k<<<dim3(16, 56), dim3(32, 8)>>>(Wq, Wk, Wv, ball);

    // fused projections (heavy 6-limb tiles first; enc-V 3-limb tiles last)
    proj_k<<<448, 256>>>(xs, xes, ball, qkv, kvenc);

    // self-attention (balanced query pairing); writes split-extended fxs directly
    attn4_k<1, 0, 1><<<512, 256>>>(qkv, nullptr, 1024, 0, qkv, 1024, 256, 512, nullptr, fxs);

    // cross-attention Q projection (split-K=2 over segment halves)
    crossq_k<<<128, 256>>>(fxs, ball, q2a, q2b);

    // cross-attention (no mask), Q = q2a + q2b
    attn4_k<0, 1, 0><<<512, 256>>>(q2a, q2b, 256, 0, kvenc, 768, 0, 256, fx2, nullptr);

    // residual + LN + FFN
    lnffn_k<<<4096, 256>>>(x, fx2, lg, lb, w1, b1, w2, b2, out);
}